// round 4
// baseline (speedup 1.0000x reference)
#include <cuda_runtime.h>
#include <math.h>

#define B 128
#define N 996
#define BN (B*N)
#define DIM 16
#define QKD 128
#define GSZ 256
#define NG 4
#define DEPTH 8
#define VOC 1024
#define ROTD 32

// ---------------- scratch (device globals; allocation-free) ----------------
__device__ __align__(16) float g_x[BN*DIM];
__device__ __align__(16) float g_v[BN*32];
__device__ __align__(16) float g_gate[BN*32];
__device__ __align__(16) float g_qo[BN*32];
__device__ __align__(16) float g_qq[BN*128];     // transformed quad_q
__device__ __align__(16) float g_kk[BN*128];     // transformed quad_k
__device__ __align__(16) float g_lq[BN*128];     // transformed lin_q
__device__ __align__(16) float g_lk[BN*128];     // transformed lin_k
__device__ __align__(16) float g_linkvp[B*8*128*32];
__device__ __align__(16) float g_linkv[B*128*32];
__device__ float g_rc[N*16];
__device__ float g_rs[N*16];
__device__ float g_hmax[BN];

#define ROT_LC 0.57564627324851142   // ln(10000)/16
#define POS_LC 1.1512925464970228    // ln(10000)/8

// ---------------- f32x2 helpers ----------------
__device__ __forceinline__ unsigned long long pk2(float a, float b) {
    unsigned long long r;
    asm("mov.b64 %0,{%1,%2};" : "=l"(r) : "f"(a), "f"(b));
    return r;
}
__device__ __forceinline__ void fma2(unsigned long long& d,
                                     unsigned long long a, unsigned long long b) {
    asm("fma.rn.f32x2 %0,%1,%2,%0;" : "+l"(d) : "l"(a), "l"(b));
}
__device__ __forceinline__ float2 up2(unsigned long long v) {
    float2 f;
    asm("mov.b64 {%0,%1},%2;" : "=f"(f.x), "=f"(f.y) : "l"(v));
    return f;
}
__device__ __forceinline__ float silu_f(float a) {
    return __fdividef(a, 1.0f + __expf(-a));
}

// ---------------- tf32 mma helpers (arch-portable, sm_80+) ----------------
__device__ __forceinline__ unsigned f2tf32(float f) {
    unsigned r;
    asm("cvt.rna.tf32.f32 %0,%1;" : "=r"(r) : "f"(f));
    return r;
}
__device__ __forceinline__ void split_tf32(float q, unsigned& h, unsigned& l) {
    h = f2tf32(q);
    l = f2tf32(q - __uint_as_float(h));
}
__device__ __forceinline__ void mma8(float* c, const unsigned* a, unsigned b0, unsigned b1) {
    asm volatile("mma.sync.aligned.m16n8k8.row.col.f32.tf32.tf32.f32 "
                 "{%0,%1,%2,%3},{%4,%5,%6,%7},{%8,%9},{%0,%1,%2,%3};"
                 : "+f"(c[0]), "+f"(c[1]), "+f"(c[2]), "+f"(c[3])
                 : "r"(a[0]), "r"(a[1]), "r"(a[2]), "r"(a[3]), "r"(b0), "r"(b1));
}
// XOR-swizzled indices (conflict-free fragment LDS)
__device__ __forceinline__ int swz128(int row, int col) {
    return row * 128 + (col ^ ((row & 7) << 2));
}
__device__ __forceinline__ int swz32(int row, int col) {
    return row * 32 + (col ^ ((row & 7) << 2));
}

// ---------------- K0: embedding + positional encoding ----------------
__global__ void k_embed(const int* __restrict__ kmer, const float* __restrict__ emb,
                        const float* __restrict__ ps) {
    int idx = blockIdx.x * blockDim.x + threadIdx.x;
    if (idx >= BN * DIM) return;
    int d = idx & 15;
    int tok = idx >> 4;
    int t = tok % N;
    int vtok = kmer[tok];
    int j = (d < 8) ? d : d - 8;
    float inv = (float)exp(-(double)j * POS_LC);
    float ang = (float)t * inv;
    float p = (d < 8) ? sinf(ang) : cosf(ang);
    g_x[idx] = emb[vtok * DIM + d] + p * ps[0];
}

// ---------------- K0b: rotary tables ----------------
__global__ void k_rot() {
    int idx = blockIdx.x * blockDim.x + threadIdx.x;
    if (idx >= N * 16) return;
    int t = idx >> 4, j = idx & 15;
    float inv = (float)exp(-(double)j * ROT_LC);
    float ang = (float)t * inv;
    g_rc[idx] = cosf(ang);
    g_rs[idx] = sinf(ang);
}

// ---------------- K1: norm + shift + projections + qk transforms ----------------
__global__ void k_proj(const float* __restrict__ ng,
                       const float* __restrict__ Wh, const float* __restrict__ bh,
                       const float* __restrict__ Wqk, const float* __restrict__ bqk,
                       const float* __restrict__ gamma, const float* __restrict__ beta) {
    __shared__ float sWh[16*64];
    __shared__ float sWqk[16*128];
    __shared__ float sbh[64];
    __shared__ float sbqk[128];
    __shared__ float xr[17][16];
    __shared__ float scl[17];
    __shared__ float nm[16][16];
    __shared__ float sqk[16][128];
    __shared__ float sg[4*128], sb2[4*128];
    __shared__ float sc[16][16], ss[16][16];
    int tid = threadIdx.x;
    int base = blockIdx.x * 16;

    for (int i = tid; i < 16*64; i += 256) sWh[i] = Wh[i];
    for (int i = tid; i < 16*128; i += 256) sWqk[i] = Wqk[i];
    if (tid < 64) sbh[tid] = bh[tid];
    if (tid < 128) sbqk[tid] = bqk[tid];
    for (int i = tid; i < 512; i += 256) { sg[i] = gamma[i]; sb2[i] = beta[i]; }
    for (int i = tid; i < 17*16; i += 256) {
        int r = i >> 4, d = i & 15;
        int f = base - 1 + r;
        xr[r][d] = (f >= 0) ? g_x[f * DIM + d] : 0.0f;
    }
    {   int i = tid >> 4, jj = tid & 15;
        int pos = (base + i) % N;
        sc[i][jj] = g_rc[pos * 16 + jj];
        ss[i][jj] = g_rs[pos * 16 + jj];
    }
    __syncthreads();
    if (tid < 17) {
        float s = 0.0f;
        #pragma unroll
        for (int d = 0; d < 16; d++) s += xr[tid][d] * xr[tid][d];
        scl[tid] = ng[0] / fmaxf(sqrtf(s) * 0.25f, 1e-5f);
    }
    __syncthreads();
    {   int i = tid >> 4, d = tid & 15;
        int flat = base + i;
        float val;
        if (d < 8) val = ((flat % N) == 0) ? 0.0f : xr[i][d] * scl[i];
        else       val = xr[i+1][d] * scl[i+1];
        nm[i][d] = val;
    }
    __syncthreads();
    for (int o = tid; o < 16 * 192; o += 256) {
        int i = o / 192, u = o % 192;
        float acc;
        if (u < 64) {
            acc = sbh[u];
            #pragma unroll
            for (int d = 0; d < 16; d++) acc += nm[i][d] * sWh[d * 64 + u];
        } else {
            int q = u - 64;
            acc = sbqk[q];
            #pragma unroll
            for (int d = 0; d < 16; d++) acc += nm[i][d] * sWqk[d * 128 + q];
        }
        float sv2 = silu_f(acc);
        int flat = base + i;
        if (u < 32)       g_v[flat * 32 + u] = sv2;
        else if (u < 64)  g_gate[flat * 32 + (u - 32)] = sv2;
        else              sqk[i][u - 64] = sv2;
    }
    __syncthreads();
    {   int i = tid >> 4;
        int d0 = (tid & 15) * 8;
        int flat = base + i;
        #pragma unroll
        for (int r = 0; r < 4; r++) {
            float* dst = (r == 0) ? g_qq : (r == 1) ? g_lq : (r == 2) ? g_kk : g_lk;
            #pragma unroll
            for (int dd = 0; dd < 8; dd += 2) {
                int d = d0 + dd;
                float v0 = sqk[i][d]   * sg[r*128 + d]   + sb2[r*128 + d];
                float v1 = sqk[i][d+1] * sg[r*128 + d+1] + sb2[r*128 + d+1];
                if (d0 < ROTD) {
                    float c = sc[i][d >> 1], s = ss[i][d >> 1];
                    float t0 = v0 * c - v1 * s;
                    v1 = v1 * c + v0 * s;
                    v0 = t0;
                }
                *(float2*)&dst[flat * 128 + d] = make_float2(v0, v1);
            }
        }
    }
}

// ---------------- K2: quadratic attention via mma.sync tf32 ----------------
// smem bytes: Qh[128x128]@0, Ql@65536, Kh chunk[64x128]@131072, Kl@163840,
//             Vh chunk[64x32]@196608, Vl@204800. Obuf reuses Kh region.
#define SQH 0
#define SQL 65536
#define SKH 131072
#define SKL 163840
#define SVH 196608
#define SVL 204800
#define ATTN_SMEM 212992

__global__ void __launch_bounds__(512, 1) k_attn() {
    extern __shared__ char smc[];
    float* smf = (float*)smc;
    unsigned* smu = (unsigned*)smc;
    int tid = threadIdx.x;
    int lane = tid & 31, wid = tid >> 5;
    int t4 = lane & 3, r8 = lane >> 2;
    int wm = wid & 7;          // M-tile (16 rows)
    int wn2 = wid >> 3;        // key-half within chunk
    int b = blockIdx.z, g = blockIdx.y, qh = blockIdx.x;
    const int bN = b * N;

    {   // Q tile 128x128 -> hi/lo tf32, swizzled
        int qrow = tid >> 2;
        int qd0 = (tid & 3) * 32;
        int pos = g * GSZ + qh * 128 + qrow;
        const float4* src = (const float4*)&g_qq[(long)(bN + pos) * 128 + qd0];
        #pragma unroll
        for (int d = 0; d < 32; d += 4) {
            float4 v = (pos < N) ? src[d >> 2] : make_float4(0,0,0,0);
            uint4 h, l;
            split_tf32(v.x, h.x, l.x); split_tf32(v.y, h.y, l.y);
            split_tf32(v.z, h.z, l.z); split_tf32(v.w, h.w, l.w);
            int idx = swz128(qrow, qd0 + d);
            *(uint4*)&smu[(SQH >> 2) + idx] = h;
            *(uint4*)&smu[(SQL >> 2) + idx] = l;
        }
    }

    float acc2[4][4];   // O accumulator: 4 n-tiles x fragment
    #pragma unroll
    for (int i = 0; i < 4; i++)
        #pragma unroll
        for (int j = 0; j < 4; j++) acc2[i][j] = 0.0f;

    int mrow = wm * 16 + r8;   // this lane's base output row (and +8)

    for (int ch = 0; ch < 4; ch++) {
        __syncthreads();
        {   // K chunk 64x128 hi/lo
            int krow = tid >> 3;
            int kd0 = (tid & 7) * 16;
            int kpos = g * GSZ + ch * 64 + krow;
            const float4* src = (const float4*)&g_kk[(long)(bN + kpos) * 128 + kd0];
            #pragma unroll
            for (int d = 0; d < 16; d += 4) {
                float4 v = (kpos < N) ? src[d >> 2] : make_float4(0,0,0,0);
                uint4 h, l;
                split_tf32(v.x, h.x, l.x); split_tf32(v.y, h.y, l.y);
                split_tf32(v.z, h.z, l.z); split_tf32(v.w, h.w, l.w);
                int idx = swz128(krow, kd0 + d);
                *(uint4*)&smu[(SKH >> 2) + idx] = h;
                *(uint4*)&smu[(SKL >> 2) + idx] = l;
            }
            // V chunk 64x32 hi/lo
            int vrow = tid >> 3;
            int ve0 = (tid & 7) * 4;
            int vpos = g * GSZ + ch * 64 + vrow;
            float4 vv = (vpos < N) ? *(const float4*)&g_v[(long)(bN + vpos) * 32 + ve0]
                                   : make_float4(0,0,0,0);
            uint4 h, l;
            split_tf32(vv.x, h.x, l.x); split_tf32(vv.y, h.y, l.y);
            split_tf32(vv.z, h.z, l.z); split_tf32(vv.w, h.w, l.w);
            int idx = swz32(vrow, ve0);
            *(uint4*)&smu[(SVH >> 2) + idx] = h;
            *(uint4*)&smu[(SVL >> 2) + idx] = l;
        }
        __syncthreads();

        // ---- sim: this warp computes rows [wm*16,+16) x keys [wn2*32,+32) ----
        float acc[4][4];
        #pragma unroll
        for (int i = 0; i < 4; i++)
            #pragma unroll
            for (int j = 0; j < 4; j++) acc[i][j] = 0.0f;

        #pragma unroll
        for (int ks = 0; ks < 16; ks++) {
            int c0 = ks * 8 + t4;
            unsigned aQh[4], aQl[4];
            aQh[0] = smu[(SQH>>2) + swz128(mrow,     c0)];
            aQh[1] = smu[(SQH>>2) + swz128(mrow + 8, c0)];
            aQh[2] = smu[(SQH>>2) + swz128(mrow,     c0 + 4)];
            aQh[3] = smu[(SQH>>2) + swz128(mrow + 8, c0 + 4)];
            aQl[0] = smu[(SQL>>2) + swz128(mrow,     c0)];
            aQl[1] = smu[(SQL>>2) + swz128(mrow + 8, c0)];
            aQl[2] = smu[(SQL>>2) + swz128(mrow,     c0 + 4)];
            aQl[3] = smu[(SQL>>2) + swz128(mrow + 8, c0 + 4)];
            #pragma unroll
            for (int nt = 0; nt < 4; nt++) {
                int krow = wn2 * 32 + nt * 8 + r8;   // chunk-local key
                unsigned bh0 = smu[(SKH>>2) + swz128(krow, c0)];
                unsigned bh1 = smu[(SKH>>2) + swz128(krow, c0 + 4)];
                unsigned bl0 = smu[(SKL>>2) + swz128(krow, c0)];
                unsigned bl1 = smu[(SKL>>2) + swz128(krow, c0 + 4)];
                mma8(acc[nt], aQh, bh0, bh1);
                mma8(acc[nt], aQh, bl0, bl1);
                mma8(acc[nt], aQl, bh0, bh1);
            }
        }

        // ---- epilogue + in-register transpose -> A fragments -> A@V ----
        #pragma unroll
        for (int nt = 0; nt < 4; nt++) {
            int colbase = ch * 64 + wn2 * 32 + nt * 8;   // key within group
            int gk0 = g * GSZ + colbase + 2 * t4;
            float e00 = fmaxf(acc[nt][0] * (1.0f/256.0f), 0.0f); e00 *= e00;
            float e01 = fmaxf(acc[nt][1] * (1.0f/256.0f), 0.0f); e01 *= e01;
            float e10 = fmaxf(acc[nt][2] * (1.0f/256.0f), 0.0f); e10 *= e10;
            float e11 = fmaxf(acc[nt][3] * (1.0f/256.0f), 0.0f); e11 *= e11;
            if (gk0     >= N) { e00 = 0.0f; e10 = 0.0f; }
            if (gk0 + 1 >= N) { e01 = 0.0f; e11 = 0.0f; }
            unsigned u00 = f2tf32(e00), u01 = f2tf32(e01);
            unsigned u10 = f2tf32(e10), u11 = f2tf32(e11);
            int srcA = (lane & ~3) | (t4 >> 1);
            int srcB = srcA + 2;
            unsigned w00A = __shfl_sync(0xffffffffu, u00, srcA);
            unsigned w01A = __shfl_sync(0xffffffffu, u01, srcA);
            unsigned w10A = __shfl_sync(0xffffffffu, u10, srcA);
            unsigned w11A = __shfl_sync(0xffffffffu, u11, srcA);
            unsigned w00B = __shfl_sync(0xffffffffu, u00, srcB);
            unsigned w01B = __shfl_sync(0xffffffffu, u01, srcB);
            unsigned w10B = __shfl_sync(0xffffffffu, u10, srcB);
            unsigned w11B = __shfl_sync(0xffffffffu, u11, srcB);
            bool odd = (t4 & 1);
            unsigned aF[4];
            aF[0] = odd ? w01A : w00A;   // (row,   key t4)
            aF[1] = odd ? w11A : w10A;   // (row+8, key t4)
            aF[2] = odd ? w01B : w00B;   // (row,   key t4+4)
            aF[3] = odd ? w11B : w10B;   // (row+8, key t4+4)
            int vr = wn2 * 32 + nt * 8 + t4;   // chunk-local V row
            #pragma unroll
            for (int ne = 0; ne < 4; ne++) {
                int e = ne * 8 + r8;
                unsigned bvh0 = smu[(SVH>>2) + swz32(vr,     e)];
                unsigned bvh1 = smu[(SVH>>2) + swz32(vr + 4, e)];
                unsigned bvl0 = smu[(SVL>>2) + swz32(vr,     e)];
                unsigned bvl1 = smu[(SVL>>2) + swz32(vr + 4, e)];
                mma8(acc2[ne], aF, bvh0, bvh1);
                mma8(acc2[ne], aF, bvl0, bvl1);
            }
        }
    }

    // ---- reduce the two key-halves and store ----
    __syncthreads();
    float* Obuf = smf + (SKH >> 2);   // [128][33]
    if (wn2 == 1) {
        #pragma unroll
        for (int ne = 0; ne < 4; ne++) {
            int e = ne * 8 + 2 * t4;
            Obuf[mrow * 33 + e]           = acc2[ne][0];
            Obuf[mrow * 33 + e + 1]       = acc2[ne][1];
            Obuf[(mrow + 8) * 33 + e]     = acc2[ne][2];
            Obuf[(mrow + 8) * 33 + e + 1] = acc2[ne][3];
        }
    }
    __syncthreads();
    if (wn2 == 0) {
        int qpos0 = g * GSZ + qh * 128 + mrow;
        #pragma unroll
        for (int ne = 0; ne < 4; ne++) {
            int e = ne * 8 + 2 * t4;
            float o0 = acc2[ne][0] + Obuf[mrow * 33 + e];
            float o1 = acc2[ne][1] + Obuf[mrow * 33 + e + 1];
            float o2 = acc2[ne][2] + Obuf[(mrow + 8) * 33 + e];
            float o3 = acc2[ne][3] + Obuf[(mrow + 8) * 33 + e + 1];
            if (qpos0 < N)
                *(float2*)&g_qo[(long)(bN + qpos0) * 32 + e] = make_float2(o0, o1);
            if (qpos0 + 8 < N)
                *(float2*)&g_qo[(long)(bN + qpos0 + 8) * 32 + e] = make_float2(o2, o3);
        }
    }
}

// ---------------- K3: linear attention KV partials (grid: 8 x B) ----------------
__global__ void k_linkvp() {
    __shared__ float slk[8][128];
    __shared__ float sv[8][32];
    int tid = threadIdx.x;
    int s = blockIdx.x, b = blockIdx.y;
    int bN = b * N;
    int p0 = s * 125, p1 = min(p0 + 125, N);
    unsigned long long acc[8];
    #pragma unroll
    for (int e = 0; e < 8; e++) acc[e] = 0ull;
    int dd = tid & 127, e0 = (tid >> 7) * 16;

    for (int pp = p0; pp < p1; pp += 8) {
        __syncthreads();
        {   int r = tid >> 5;
            int d4 = (tid & 31) * 4;
            int pos = pp + r;
            float4 v = (pos < p1) ? *(const float4*)&g_lk[(long)(bN + pos) * 128 + d4]
                                  : make_float4(0,0,0,0);
            *(float4*)&slk[r][d4] = v;
            int e = tid & 31;
            sv[r][e] = (pos < p1) ? g_v[(long)(bN + pos) * 32 + e] : 0.0f;
        }
        __syncthreads();
        #pragma unroll
        for (int r = 0; r < 8; r++) {
            float lv = slk[r][dd];
            unsigned long long ld = pk2(lv, lv);
            const ulonglong2* vp = (const ulonglong2*)&sv[r][e0];
            ulonglong2 va = vp[0], vb = vp[1], vc = vp[2], vd = vp[3];
            fma2(acc[0], ld, va.x); fma2(acc[1], ld, va.y);
            fma2(acc[2], ld, vb.x); fma2(acc[3], ld, vb.y);
            fma2(acc[4], ld, vc.x); fma2(acc[5], ld, vc.y);
            fma2(acc[6], ld, vd.x); fma2(acc[7], ld, vd.y);
        }
    }
    float* dst = &g_linkvp[((long)(b * 8 + s) * 128 + dd) * 32 + e0];
    #pragma unroll
    for (int e = 0; e < 8; e++) {
        float2 f = up2(acc[e]);
        *(float2*)&dst[e * 2] = f;
    }
}

// ---------------- K3b: reduce partials ----------------
__global__ void k_kvred() {
    int b = blockIdx.x, tid = threadIdx.x;
    for (int idx = tid; idx < 4096; idx += 256) {
        float s = 0.0f;
        #pragma unroll
        for (int k2 = 0; k2 < 8; k2++) s += g_linkvp[(long)(b * 8 + k2) * 4096 + idx];
        g_linkv[(long)b * 4096 + idx] = s * (1.0f / (float)N);
    }
}

// ---------------- K4: lin_out + gate + Wo + residual (grid: 12 x B) ----------------
__global__ void k_out(const float* __restrict__ Wo, const float* __restrict__ bo) {
    __shared__ float skv[4096];
    __shared__ float sWo[32*16];
    __shared__ float sbo[16];
    __shared__ float ovs[8][32];
    int tid = threadIdx.x;
    int b = blockIdx.y, ch = blockIdx.x;
    int bN = b * N;
    for (int i = tid; i < 1024; i += 256)
        ((float4*)skv)[i] = ((const float4*)&g_linkv[(long)b * 4096])[i];
    for (int i = tid; i < 512; i += 256) sWo[i] = Wo[i];
    if (tid < 16) sbo[tid] = bo[tid];
    __syncthreads();

    int w = tid >> 5, lane = tid & 31;
    int t0 = ch * 83, t1 = t0 + 83;   // 12*83 = 996
    for (int tok = t0 + w; tok < t1; tok += 8) {
        int tf = bN + tok;
        float4 lq4 = *(const float4*)&g_lq[(long)tf * 128 + lane * 4];
        float lqa[4] = {lq4.x, lq4.y, lq4.z, lq4.w};
        float acc = g_qo[(long)tf * 32 + lane];
        #pragma unroll
        for (int comp = 0; comp < 4; comp++) {
            #pragma unroll
            for (int src = 0; src < 32; src++) {
                float lv = __shfl_sync(0xffffffffu, lqa[comp], src);
                acc += lv * skv[(src * 4 + comp) * 32 + lane];
            }
        }
        acc *= g_gate[(long)tf * 32 + lane];
        ovs[w][lane] = acc;
        __syncwarp();
        if (lane < 16) {
            float y = sbo[lane];
            #pragma unroll
            for (int e = 0; e < 32; e++) y += ovs[w][e] * sWo[e * DIM + lane];
            g_x[(long)tf * DIM + lane] += y;
        }
        __syncwarp();
    }
}

// ---------------- K5: final norm + logits + vocab max ----------------
#define LOGITS_SMEM ((16*1024 + 1024 + 16*16) * 4)
__global__ void k_logits(const float* __restrict__ fg, const float* __restrict__ Wl,
                         const float* __restrict__ blv) {
    extern __shared__ float sm[];
    float* sW = sm;
    float* sb = sW + 16 * 1024;
    float* xn = sb + 1024;
    __shared__ float wred[8];
    __shared__ float xs[16];
    int tid = threadIdx.x;
    int base = blockIdx.x * 16;

    for (int i = tid; i < (16 * 1024) / 4; i += 256)
        ((float4*)sW)[i] = ((const float4*)Wl)[i];
    for (int i = tid; i < 1024; i += 256) sb[i] = blv[i];
    {   int tt = tid >> 4, d = tid & 15;
        xn[tt * 16 + d] = g_x[(long)(base + tt) * DIM + d];
    }
    __syncthreads();
    if (tid < 16) {
        float s = 0.0f;
        #pragma unroll
        for (int d = 0; d < 16; d++) { float v = xn[tid * 16 + d]; s += v * v; }
        xs[tid] = fg[0] / fmaxf(sqrtf(s) * 0.25f, 1e-5f);
    }
    __syncthreads();
    {   int tt = tid >> 4, d = tid & 15;
        xn[tt * 16 + d] *= xs[tt];
    }
    __syncthreads();
    int warp = tid >> 5, lane = tid & 31;
    int v0 = tid * 4;
    for (int tt = 0; tt < 16; tt++) {
        float s0 = sb[v0], s1 = sb[v0 + 1], s2 = sb[v0 + 2], s3 = sb[v0 + 3];
        #pragma unroll
        for (int d = 0; d < 16; d++) {
            float xv = xn[tt * 16 + d];
            float4 wv = *(const float4*)&sW[d * 1024 + v0];
            s0 += xv * wv.x; s1 += xv * wv.y; s2 += xv * wv.z; s3 += xv * wv.w;
        }
        float m = fmaxf(fmaxf(s0, s1), fmaxf(s2, s3));
        #pragma unroll
        for (int off = 16; off > 0; off >>= 1)
            m = fmaxf(m, __shfl_xor_sync(0xffffffff, m, off));
        if (lane == 0) wred[warp] = m;
        __syncthreads();
        if (tid == 0) {
            float mm = wred[0];
            #pragma unroll
            for (int j = 1; j < 8; j++) mm = fmaxf(mm, wred[j]);
            g_hmax[base + tt] = mm;
        }
        __syncthreads();
    }
}

// ---------------- K6: head MLP ----------------
__global__ void k_head(const float* __restrict__ W1, const float* __restrict__ b1,
                       const float* __restrict__ W2, const float* __restrict__ b2,
                       float* __restrict__ out) {
    __shared__ float red[8][32];
    __shared__ float rr[32];
    int tid = threadIdx.x;
    int b = blockIdx.x;
    int col = tid & 31, seg = tid >> 5;
    float acc = 0.0f;
    int t0 = seg * 125;
    int t1 = min(t0 + 125, N);
    for (int t = t0; t < t1; t++)
        acc += g_hmax[(long)b * N + t] * W1[t * 32 + col];
    red[seg][col] = acc;
    __syncthreads();
    if (tid < 32) {
        float s = b1[tid];
        #pragma unroll
        for (int k = 0; k < 8; k++) s += red[k][tid];
        rr[tid] = fmaxf(s, 0.0f);
    }
    __syncthreads();
    if (tid == 0) {
        float o = b2[0];
        #pragma unroll
        for (int j = 0; j < 32; j++) o += rr[j] * W2[j];
        out[b] = o;
    }
}

// ---------------- launch ----------------
extern "C" void kernel_launch(void* const* d_in, const int* in_sizes, int n_in,
                              void* d_out, int out_size) {
    const int*   kmer    = (const int*)  d_in[0];
    const float* emb     = (const float*)d_in[1];
    const float* psc     = (const float*)d_in[2];
    const float* norm_g  = (const float*)d_in[3];
    const float* Wh      = (const float*)d_in[4];
    const float* bh      = (const float*)d_in[5];
    const float* Wqk     = (const float*)d_in[6];
    const float* bqk     = (const float*)d_in[7];
    const float* gamma   = (const float*)d_in[8];
    const float* beta    = (const float*)d_in[9];
    const float* Wo      = (const float*)d_in[10];
    const float* bo      = (const float*)d_in[11];
    const float* fg      = (const float*)d_in[12];
    const float* Wl      = (const float*)d_in[13];
    const float* bl      = (const float*)d_in[14];
    const float* W1      = (const float*)d_in[15];
    const float* b1      = (const float*)d_in[16];
    const float* W2      = (const float*)d_in[17];
    const float* b2      = (const float*)d_in[18];
    float* out = (float*)d_out;

    cudaFuncSetAttribute(k_attn,   cudaFuncAttributeMaxDynamicSharedMemorySize, ATTN_SMEM);
    cudaFuncSetAttribute(k_logits, cudaFuncAttributeMaxDynamicSharedMemorySize, LOGITS_SMEM);

    k_embed<<<(BN * DIM + 255) / 256, 256>>>(kmer, emb, psc);
    k_rot<<<(N * 16 + 255) / 256, 256>>>();

    for (int l = 0; l < DEPTH; l++) {
        k_proj<<<BN / 16, 256>>>(norm_g + l,
                                 Wh + (long)l * 16 * 64, bh + (long)l * 64,
                                 Wqk + (long)l * 16 * 128, bqk + (long)l * 128,
                                 gamma + (long)l * 4 * 128, beta + (long)l * 4 * 128);
        k_attn<<<dim3(2, NG, B), 512, ATTN_SMEM>>>();
        k_linkvp<<<dim3(8, B), 256>>>();
        k_kvred<<<B, 256>>>();
        k_out<<<dim3(12, B), 256>>>(Wo + (long)l * 32 * DIM, bo + (long)l * DIM);
    }

    k_logits<<<BN / 16, 256, LOGITS_SMEM>>>(fg, Wl, bl);
    k_head<<<B, 256>>>(W1, b1, W2, b2, out);
    (void)in_sizes; (void)n_in; (void)out_size;
}

// round 5
// speedup vs baseline: 1.3645x; 1.3645x over previous
#include <cuda_runtime.h>
#include <math.h>

#define B 128
#define N 996
#define BN (B*N)
#define DIM 16
#define QKD 128
#define GSZ 256
#define NG 4
#define DEPTH 8
#define VOC 1024
#define ROTD 32

// ---------------- scratch (device globals; allocation-free) ----------------
__device__ __align__(16) float g_x[BN*DIM];
__device__ __align__(16) float g_v[BN*32];
__device__ __align__(16) float g_gate[BN*32];
__device__ __align__(16) float g_qo[BN*32];
__device__ __align__(16) float g_qq[BN*128];     // transformed quad_q
__device__ __align__(16) float g_kk[BN*128];     // transformed quad_k
__device__ __align__(16) float g_lq[BN*128];     // transformed lin_q
__device__ __align__(16) float g_lk[BN*128];     // transformed lin_k
__device__ __align__(16) float g_linkvp[B*8*128*32];
__device__ float g_rc[N*16];
__device__ float g_rs[N*16];
__device__ float g_hmax[BN];

#define ROT_LC 0.57564627324851142   // ln(10000)/16
#define POS_LC 1.1512925464970228    // ln(10000)/8

// ---------------- f32x2 helpers ----------------
__device__ __forceinline__ unsigned long long pk2(float a, float b) {
    unsigned long long r;
    asm("mov.b64 %0,{%1,%2};" : "=l"(r) : "f"(a), "f"(b));
    return r;
}
__device__ __forceinline__ void fma2(unsigned long long& d,
                                     unsigned long long a, unsigned long long b) {
    asm("fma.rn.f32x2 %0,%1,%2,%0;" : "+l"(d) : "l"(a), "l"(b));
}
__device__ __forceinline__ float2 up2(unsigned long long v) {
    float2 f;
    asm("mov.b64 {%0,%1},%2;" : "=f"(f.x), "=f"(f.y) : "l"(v));
    return f;
}
__device__ __forceinline__ float silu_f(float a) {
    return __fdividef(a, 1.0f + __expf(-a));
}

// ---------------- K0: embedding + positional encoding ----------------
__global__ void k_embed(const int* __restrict__ kmer, const float* __restrict__ emb,
                        const float* __restrict__ ps) {
    int idx = blockIdx.x * blockDim.x + threadIdx.x;
    if (idx >= BN * DIM) return;
    int d = idx & 15;
    int tok = idx >> 4;
    int t = tok % N;
    int vtok = kmer[tok];
    int j = (d < 8) ? d : d - 8;
    float inv = (float)exp(-(double)j * POS_LC);
    float ang = (float)t * inv;
    float p = (d < 8) ? sinf(ang) : cosf(ang);
    g_x[idx] = emb[vtok * DIM + d] + p * ps[0];
}

// ---------------- K0b: rotary tables ----------------
__global__ void k_rot() {
    int idx = blockIdx.x * blockDim.x + threadIdx.x;
    if (idx >= N * 16) return;
    int t = idx >> 4, j = idx & 15;
    float inv = (float)exp(-(double)j * ROT_LC);
    float ang = (float)t * inv;
    g_rc[idx] = cosf(ang);
    g_rs[idx] = sinf(ang);
}

// ---------------- K1: norm + shift + projections + qk transforms ----------------
__global__ void k_proj(const float* __restrict__ ng,
                       const float* __restrict__ Wh, const float* __restrict__ bh,
                       const float* __restrict__ Wqk, const float* __restrict__ bqk,
                       const float* __restrict__ gamma, const float* __restrict__ beta) {
    __shared__ float sWh[16*64];
    __shared__ float sWqk[16*128];
    __shared__ float sbh[64];
    __shared__ float sbqk[128];
    __shared__ float xr[17][16];
    __shared__ float scl[17];
    __shared__ float nm[16][16];
    __shared__ float sqk[16][128];
    __shared__ float sg[4*128], sb2[4*128];
    __shared__ float sc[16][16], ss[16][16];
    int tid = threadIdx.x;
    int base = blockIdx.x * 16;

    for (int i = tid; i < 16*64; i += 256) sWh[i] = Wh[i];
    for (int i = tid; i < 16*128; i += 256) sWqk[i] = Wqk[i];
    if (tid < 64) sbh[tid] = bh[tid];
    if (tid < 128) sbqk[tid] = bqk[tid];
    for (int i = tid; i < 512; i += 256) { sg[i] = gamma[i]; sb2[i] = beta[i]; }
    for (int i = tid; i < 17*16; i += 256) {
        int r = i >> 4, d = i & 15;
        int f = base - 1 + r;
        xr[r][d] = (f >= 0) ? g_x[f * DIM + d] : 0.0f;
    }
    {   int i = tid >> 4, jj = tid & 15;
        int pos = (base + i) % N;
        sc[i][jj] = g_rc[pos * 16 + jj];
        ss[i][jj] = g_rs[pos * 16 + jj];
    }
    __syncthreads();
    if (tid < 17) {
        float s = 0.0f;
        #pragma unroll
        for (int d = 0; d < 16; d++) s += xr[tid][d] * xr[tid][d];
        scl[tid] = ng[0] / fmaxf(sqrtf(s) * 0.25f, 1e-5f);
    }
    __syncthreads();
    {   int i = tid >> 4, d = tid & 15;
        int flat = base + i;
        float val;
        if (d < 8) val = ((flat % N) == 0) ? 0.0f : xr[i][d] * scl[i];
        else       val = xr[i+1][d] * scl[i+1];
        nm[i][d] = val;
    }
    __syncthreads();
    for (int o = tid; o < 16 * 192; o += 256) {
        int i = o / 192, u = o % 192;
        float acc;
        if (u < 64) {
            acc = sbh[u];
            #pragma unroll
            for (int d = 0; d < 16; d++) acc += nm[i][d] * sWh[d * 64 + u];
        } else {
            int q = u - 64;
            acc = sbqk[q];
            #pragma unroll
            for (int d = 0; d < 16; d++) acc += nm[i][d] * sWqk[d * 128 + q];
        }
        float sv2 = silu_f(acc);
        int flat = base + i;
        if (u < 32)       g_v[flat * 32 + u] = sv2;
        else if (u < 64)  g_gate[flat * 32 + (u - 32)] = sv2;
        else              sqk[i][u - 64] = sv2;
    }
    __syncthreads();
    {   int i = tid >> 4;
        int d0 = (tid & 15) * 8;
        int flat = base + i;
        #pragma unroll
        for (int r = 0; r < 4; r++) {
            float* dst = (r == 0) ? g_qq : (r == 1) ? g_lq : (r == 2) ? g_kk : g_lk;
            #pragma unroll
            for (int dd = 0; dd < 8; dd += 2) {
                int d = d0 + dd;
                float v0 = sqk[i][d]   * sg[r*128 + d]   + sb2[r*128 + d];
                float v1 = sqk[i][d+1] * sg[r*128 + d+1] + sb2[r*128 + d+1];
                if (d0 < ROTD) {
                    float c = sc[i][d >> 1], s = ss[i][d >> 1];
                    float t0 = v0 * c - v1 * s;
                    v1 = v1 * c + v0 * s;
                    v0 = t0;
                }
                *(float2*)&dst[flat * 128 + d] = make_float2(v0, v1);
            }
        }
    }
}

// ---------------- K2: quadratic attention, f32x2, 512 threads ----------------
// smem floats: Qs[128][132] + Kt[128][132] + As[128][130] + Vs[128][32]
#define QS2 132
#define KT2 132
#define AS2 130
#define ATTN_SMEM ((128*QS2 + 128*KT2 + 128*AS2 + 128*32) * 4)   // 218112 B

__global__ void __launch_bounds__(512, 1) k_attn() {
    extern __shared__ float sm[];
    float* Qs = sm;                  // [row][kdim]
    float* Kt = Qs + 128 * QS2;      // [kdim][key]
    float* As = Kt + 128 * KT2;      // [row][key]
    float* Vs = As + 128 * AS2;      // [key][32]
    int tid = threadIdx.x;
    int b = blockIdx.z, g = blockIdx.y, qh = blockIdx.x;
    const int bN = b * N;

    {   // Q tile 128x128 row-major
        int row = tid >> 2;
        int d0 = (tid & 3) * 32;
        int pos = g * GSZ + qh * 128 + row;
        const float4* src = (const float4*)&g_qq[(long)(bN + pos) * 128 + d0];
        #pragma unroll
        for (int d = 0; d < 32; d += 4) {
            float4 v = (pos < N) ? src[d >> 2] : make_float4(0,0,0,0);
            *(float4*)&Qs[row * QS2 + d0 + d] = v;
        }
    }

    int tx = tid & 15;          // col group: cols 2tx+32c (+1), c=0..3
    int tyy = tid >> 4;         // rows 4tyy .. 4tyy+3
    int oi = tid >> 2;          // stage B row
    int eg = (tid & 3) * 8;     // stage B dim-octet

    unsigned long long oacc[4];
    #pragma unroll
    for (int e = 0; e < 4; e++) oacc[e] = 0ull;

    for (int kc = 0; kc < 2; kc++) {
        __syncthreads();
        {   // K chunk 128 keys, transposed; V chunk
            int col = tid & 127;
            int dg = tid >> 7;               // 0..3 -> dims [32dg,32dg+32)
            int pos = g * GSZ + kc * 128 + col;
            const float4* src = (const float4*)&g_kk[(long)(bN + pos) * 128 + dg * 32];
            #pragma unroll
            for (int d = 0; d < 32; d += 4) {
                float4 v = (pos < N) ? src[d >> 2] : make_float4(0,0,0,0);
                Kt[(dg * 32 + d + 0) * KT2 + col] = v.x;
                Kt[(dg * 32 + d + 1) * KT2 + col] = v.y;
                Kt[(dg * 32 + d + 2) * KT2 + col] = v.z;
                Kt[(dg * 32 + d + 3) * KT2 + col] = v.w;
            }
            int rr = tid >> 2;
            int e0 = (tid & 3) * 8;
            int pv = g * GSZ + kc * 128 + rr;
            const float4* vsrc = (const float4*)&g_v[(long)(bN + pv) * 32 + e0];
            float4 v0 = (pv < N) ? vsrc[0] : make_float4(0,0,0,0);
            float4 v1 = (pv < N) ? vsrc[1] : make_float4(0,0,0,0);
            *(float4*)&Vs[rr * 32 + e0]     = v0;
            *(float4*)&Vs[rr * 32 + e0 + 4] = v1;
        }
        __syncthreads();
        {   // stage A: sim rows {4tyy..+3} x cols {2tx+32c,+1}
            unsigned long long acc[4][4];
            #pragma unroll
            for (int r = 0; r < 4; r++)
                #pragma unroll
                for (int c = 0; c < 4; c++) acc[r][c] = 0ull;
            #pragma unroll 4
            for (int kk = 0; kk < 128; kk++) {
                unsigned long long kp[4];
                #pragma unroll
                for (int c = 0; c < 4; c++)
                    kp[c] = *(const unsigned long long*)&Kt[kk * KT2 + 2 * tx + 32 * c];
                #pragma unroll
                for (int r = 0; r < 4; r++) {
                    float qv = Qs[(4 * tyy + r) * QS2 + kk];
                    unsigned long long qd = pk2(qv, qv);
                    #pragma unroll
                    for (int c = 0; c < 4; c++) fma2(acc[r][c], qd, kp[c]);
                }
            }
            int kbase = g * GSZ + kc * 128;
            #pragma unroll
            for (int r = 0; r < 4; r++) {
                int row = 4 * tyy + r;
                #pragma unroll
                for (int c = 0; c < 4; c++) {
                    float2 f = up2(acc[r][c]);
                    int c0 = 2 * tx + 32 * c;
                    float s0 = fmaxf(f.x * (1.0f/256.0f), 0.0f); s0 *= s0;
                    float s1 = fmaxf(f.y * (1.0f/256.0f), 0.0f); s1 *= s1;
                    if (kbase + c0     >= N) s0 = 0.0f;
                    if (kbase + c0 + 1 >= N) s1 = 0.0f;
                    *(unsigned long long*)&As[row * AS2 + c0] = pk2(s0, s1);
                }
            }
        }
        __syncthreads();
        {   // stage B: O[oi][eg..eg+7] += A * V
            #pragma unroll 4
            for (int j = 0; j < 128; j++) {
                float aij = As[oi * AS2 + j];
                unsigned long long ad = pk2(aij, aij);
                const unsigned long long* vp = (const unsigned long long*)&Vs[j * 32 + eg];
                fma2(oacc[0], ad, vp[0]);
                fma2(oacc[1], ad, vp[1]);
                fma2(oacc[2], ad, vp[2]);
                fma2(oacc[3], ad, vp[3]);
            }
        }
    }
    int qpos = g * GSZ + qh * 128 + oi;
    if (qpos < N) {
        float* dst = &g_qo[(long)(bN + qpos) * 32 + eg];
        #pragma unroll
        for (int e = 0; e < 4; e++) {
            float2 f = up2(oacc[e]);
            *(float2*)&dst[e * 2] = f;
        }
    }
}

// ---------------- K3: linear attention KV partials (grid: 8 x B) ----------------
__global__ void k_linkvp() {
    __shared__ float slk[8][128];
    __shared__ float sv[8][32];
    int tid = threadIdx.x;
    int s = blockIdx.x, b = blockIdx.y;
    int bN = b * N;
    int p0 = s * 125, p1 = min(p0 + 125, N);
    unsigned long long acc[8];
    #pragma unroll
    for (int e = 0; e < 8; e++) acc[e] = 0ull;
    int dd = tid & 127, e0 = (tid >> 7) * 16;

    for (int pp = p0; pp < p1; pp += 8) {
        __syncthreads();
        {   int r = tid >> 5;
            int d4 = (tid & 31) * 4;
            int pos = pp + r;
            float4 v = (pos < p1) ? *(const float4*)&g_lk[(long)(bN + pos) * 128 + d4]
                                  : make_float4(0,0,0,0);
            *(float4*)&slk[r][d4] = v;
            int e = tid & 31;
            sv[r][e] = (pos < p1) ? g_v[(long)(bN + pos) * 32 + e] : 0.0f;
        }
        __syncthreads();
        #pragma unroll
        for (int r = 0; r < 8; r++) {
            float lv = slk[r][dd];
            unsigned long long ld = pk2(lv, lv);
            const ulonglong2* vp = (const ulonglong2*)&sv[r][e0];
            ulonglong2 va = vp[0], vb = vp[1], vc = vp[2], vd = vp[3];
            fma2(acc[0], ld, va.x); fma2(acc[1], ld, va.y);
            fma2(acc[2], ld, vb.x); fma2(acc[3], ld, vb.y);
            fma2(acc[4], ld, vc.x); fma2(acc[5], ld, vc.y);
            fma2(acc[6], ld, vd.x); fma2(acc[7], ld, vd.y);
        }
    }
    float* dst = &g_linkvp[((long)(b * 8 + s) * 128 + dd) * 32 + e0];
    #pragma unroll
    for (int e = 0; e < 8; e++) {
        float2 f = up2(acc[e]);
        *(float2*)&dst[e * 2] = f;
    }
}

// ---------------- K4: KV reduce + lin_out + gate + Wo + residual ----------------
__global__ void k_out(const float* __restrict__ Wo, const float* __restrict__ bo) {
    __shared__ float skv[4096];
    __shared__ float sWo[32*16];
    __shared__ float sbo[16];
    __shared__ float ovs[8][32];
    int tid = threadIdx.x;
    int b = blockIdx.y, ch = blockIdx.x;
    int bN = b * N;
    const float inv_n = 1.0f / (float)N;
    for (int i = tid; i < 1024; i += 256) {
        float4 s = make_float4(0,0,0,0);
        #pragma unroll
        for (int k2 = 0; k2 < 8; k2++) {
            float4 p = ((const float4*)&g_linkvp[(long)(b * 8 + k2) * 4096])[i];
            s.x += p.x; s.y += p.y; s.z += p.z; s.w += p.w;
        }
        ((float4*)skv)[i] = make_float4(s.x * inv_n, s.y * inv_n, s.z * inv_n, s.w * inv_n);
    }
    for (int i = tid; i < 512; i += 256) sWo[i] = Wo[i];
    if (tid < 16) sbo[tid] = bo[tid];
    __syncthreads();

    int w = tid >> 5, lane = tid & 31;
    int t0 = ch * 83, t1 = t0 + 83;   // 12*83 = 996
    for (int tok = t0 + w; tok < t1; tok += 8) {
        int tf = bN + tok;
        float4 lq4 = *(const float4*)&g_lq[(long)tf * 128 + lane * 4];
        float lqa[4] = {lq4.x, lq4.y, lq4.z, lq4.w};
        float acc = g_qo[(long)tf * 32 + lane];
        #pragma unroll
        for (int comp = 0; comp < 4; comp++) {
            #pragma unroll
            for (int src = 0; src < 32; src++) {
                float lv = __shfl_sync(0xffffffffu, lqa[comp], src);
                acc += lv * skv[(src * 4 + comp) * 32 + lane];
            }
        }
        acc *= g_gate[(long)tf * 32 + lane];
        ovs[w][lane] = acc;
        __syncwarp();
        if (lane < 16) {
            float y = sbo[lane];
            #pragma unroll
            for (int e = 0; e < 32; e++) y += ovs[w][e] * sWo[e * DIM + lane];
            g_x[(long)tf * DIM + lane] += y;
        }
        __syncwarp();
    }
}

// ---------------- K5: final norm + logits + vocab max ----------------
#define LOGITS_SMEM ((16*1024 + 1024 + 16*16) * 4)
__global__ void k_logits(const float* __restrict__ fg, const float* __restrict__ Wl,
                         const float* __restrict__ blv) {
    extern __shared__ float sm[];
    float* sW = sm;
    float* sb = sW + 16 * 1024;
    float* xn = sb + 1024;
    __shared__ float wred[8];
    __shared__ float xs[16];
    int tid = threadIdx.x;
    int base = blockIdx.x * 16;

    for (int i = tid; i < (16 * 1024) / 4; i += 256)
        ((float4*)sW)[i] = ((const float4*)Wl)[i];
    for (int i = tid; i < 1024; i += 256) sb[i] = blv[i];
    {   int tt = tid >> 4, d = tid & 15;
        xn[tt * 16 + d] = g_x[(long)(base + tt) * DIM + d];
    }
    __syncthreads();
    if (tid < 16) {
        float s = 0.0f;
        #pragma unroll
        for (int d = 0; d < 16; d++) { float v = xn[tid * 16 + d]; s += v * v; }
        xs[tid] = fg[0] / fmaxf(sqrtf(s) * 0.25f, 1e-5f);
    }
    __syncthreads();
    {   int tt = tid >> 4, d = tid & 15;
        xn[tt * 16 + d] *= xs[tt];
    }
    __syncthreads();
    int warp = tid >> 5, lane = tid & 31;
    int v0 = tid * 4;
    for (int tt = 0; tt < 16; tt++) {
        float s0 = sb[v0], s1 = sb[v0 + 1], s2 = sb[v0 + 2], s3 = sb[v0 + 3];
        #pragma unroll
        for (int d = 0; d < 16; d++) {
            float xv = xn[tt * 16 + d];
            float4 wv = *(const float4*)&sW[d * 1024 + v0];
            s0 += xv * wv.x; s1 += xv * wv.y; s2 += xv * wv.z; s3 += xv * wv.w;
        }
        float m = fmaxf(fmaxf(s0, s1), fmaxf(s2, s3));
        #pragma unroll
        for (int off = 16; off > 0; off >>= 1)
            m = fmaxf(m, __shfl_xor_sync(0xffffffff, m, off));
        if (lane == 0) wred[warp] = m;
        __syncthreads();
        if (tid == 0) {
            float mm = wred[0];
            #pragma unroll
            for (int j = 1; j < 8; j++) mm = fmaxf(mm, wred[j]);
            g_hmax[base + tt] = mm;
        }
        __syncthreads();
    }
}

// ---------------- K6: head MLP ----------------
__global__ void k_head(const float* __restrict__ W1, const float* __restrict__ b1,
                       const float* __restrict__ W2, const float* __restrict__ b2,
                       float* __restrict__ out) {
    __shared__ float red[8][32];
    __shared__ float rr[32];
    int tid = threadIdx.x;
    int b = blockIdx.x;
    int col = tid & 31, seg = tid >> 5;
    float acc = 0.0f;
    int t0 = seg * 125;
    int t1 = min(t0 + 125, N);
    for (int t = t0; t < t1; t++)
        acc += g_hmax[(long)b * N + t] * W1[t * 32 + col];
    red[seg][col] = acc;
    __syncthreads();
    if (tid < 32) {
        float s = b1[tid];
        #pragma unroll
        for (int k = 0; k < 8; k++) s += red[k][tid];
        rr[tid] = fmaxf(s, 0.0f);
    }
    __syncthreads();
    if (tid == 0) {
        float o = b2[0];
        #pragma unroll
        for (int j = 0; j < 32; j++) o += rr[j] * W2[j];
        out[b] = o;
    }
}

// ---------------- launch ----------------
extern "C" void kernel_launch(void* const* d_in, const int* in_sizes, int n_in,
                              void* d_out, int out_size) {
    const int*   kmer    = (const int*)  d_in[0];
    const float* emb     = (const float*)d_in[1];
    const float* psc     = (const float*)d_in[2];
    const float* norm_g  = (const float*)d_in[3];
    const float* Wh      = (const float*)d_in[4];
    const float* bh      = (const float*)d_in[5];
    const float* Wqk     = (const float*)d_in[6];
    const float* bqk     = (const float*)d_in[7];
    const float* gamma   = (const float*)d_in[8];
    const float* beta    = (const float*)d_in[9];
    const float* Wo      = (const float*)d_in[10];
    const float* bo      = (const float*)d_in[11];
    const float* fg      = (const float*)d_in[12];
    const float* Wl      = (const float*)d_in[13];
    const float* bl      = (const float*)d_in[14];
    const float* W1      = (const float*)d_in[15];
    const float* b1      = (const float*)d_in[16];
    const float* W2      = (const float*)d_in[17];
    const float* b2      = (const float*)d_in[18];
    float* out = (float*)d_out;

    cudaFuncSetAttribute(k_attn,   cudaFuncAttributeMaxDynamicSharedMemorySize, ATTN_SMEM);
    cudaFuncSetAttribute(k_logits, cudaFuncAttributeMaxDynamicSharedMemorySize, LOGITS_SMEM);

    k_embed<<<(BN * DIM + 255) / 256, 256>>>(kmer, emb, psc);
    k_rot<<<(N * 16 + 255) / 256, 256>>>();

    for (int l = 0; l < DEPTH; l++) {
        k_proj<<<BN / 16, 256>>>(norm_g + l,
                                 Wh + (long)l * 16 * 64, bh + (long)l * 64,
                                 Wqk + (long)l * 16 * 128, bqk + (long)l * 128,
                                 gamma + (long)l * 4 * 128, beta + (long)l * 4 * 128);
        k_attn<<<dim3(2, NG, B), 512, ATTN_SMEM>>>();
        k_linkvp<<<dim3(8, B), 256>>>();
        k_out<<<dim3(12, B), 256>>>(Wo + (long)l * 32 * DIM, bo + (long)l * DIM);
    }

    k_logits<<<BN / 16, 256, LOGITS_SMEM>>>(fg, Wl, bl);
    k_head<<<B, 256>>>(W1, b1, W2, b2, out);
    (void)in_sizes; (void)n_in; (void)out_size;
}

// round 6
// speedup vs baseline: 1.3686x; 1.0030x over previous
#include <cuda_runtime.h>
#include <math.h>

#define B 128
#define N 996
#define BN (B*N)
#define DIM 16
#define QKD 128
#define GSZ 256
#define NG 4
#define DEPTH 8
#define VOC 1024
#define ROTD 32

// ---------------- scratch (device globals; allocation-free) ----------------
__device__ __align__(16) float g_x[BN*DIM];
__device__ __align__(16) float g_v[BN*32];
__device__ __align__(16) float g_gate[BN*32];
__device__ __align__(16) float g_qo[BN*32];
__device__ __align__(16) float g_qq[BN*128];     // transformed quad_q
__device__ __align__(16) float g_kk[BN*128];     // transformed quad_k
__device__ __align__(16) float g_lq[BN*128];     // transformed lin_q
__device__ __align__(16) float g_lk[BN*128];     // transformed lin_k
__device__ __align__(16) float g_linkvp[B*8*128*32];
__device__ float g_rc[N*16];
__device__ float g_rs[N*16];
__device__ float g_hmax[BN];

#define ROT_LC 0.57564627324851142   // ln(10000)/16
#define POS_LC 1.1512925464970228    // ln(10000)/8

// ---------------- f32x2 helpers ----------------
__device__ __forceinline__ unsigned long long pk2(float a, float b) {
    unsigned long long r;
    asm("mov.b64 %0,{%1,%2};" : "=l"(r) : "f"(a), "f"(b));
    return r;
}
__device__ __forceinline__ void fma2(unsigned long long& d,
                                     unsigned long long a, unsigned long long b) {
    asm("fma.rn.f32x2 %0,%1,%2,%0;" : "+l"(d) : "l"(a), "l"(b));
}
__device__ __forceinline__ float2 up2(unsigned long long v) {
    float2 f;
    asm("mov.b64 {%0,%1},%2;" : "=f"(f.x), "=f"(f.y) : "l"(v));
    return f;
}
__device__ __forceinline__ float silu_f(float a) {
    return __fdividef(a, 1.0f + __expf(-a));
}

// ---------------- K0: embedding + positional encoding ----------------
__global__ void k_embed(const int* __restrict__ kmer, const float* __restrict__ emb,
                        const float* __restrict__ ps) {
    int idx = blockIdx.x * blockDim.x + threadIdx.x;
    if (idx >= BN * DIM) return;
    int d = idx & 15;
    int tok = idx >> 4;
    int t = tok % N;
    int vtok = kmer[tok];
    int j = (d < 8) ? d : d - 8;
    float inv = (float)exp(-(double)j * POS_LC);
    float ang = (float)t * inv;
    float p = (d < 8) ? sinf(ang) : cosf(ang);
    g_x[idx] = emb[vtok * DIM + d] + p * ps[0];
}

// ---------------- K0b: rotary tables ----------------
__global__ void k_rot() {
    int idx = blockIdx.x * blockDim.x + threadIdx.x;
    if (idx >= N * 16) return;
    int t = idx >> 4, j = idx & 15;
    float inv = (float)exp(-(double)j * ROT_LC);
    float ang = (float)t * inv;
    g_rc[idx] = cosf(ang);
    g_rs[idx] = sinf(ang);
}

// ---------------- K1: norm + shift + projections + qk transforms ----------------
__global__ void k_proj(const float* __restrict__ ng,
                       const float* __restrict__ Wh, const float* __restrict__ bh,
                       const float* __restrict__ Wqk, const float* __restrict__ bqk,
                       const float* __restrict__ gamma, const float* __restrict__ beta) {
    __shared__ float sWh[16*64];
    __shared__ float sWqk[16*128];
    __shared__ float sbh[64];
    __shared__ float sbqk[128];
    __shared__ float xr[17][16];
    __shared__ float scl[17];
    __shared__ float nm[16][16];
    __shared__ float sqk[16][128];
    __shared__ float sg[4*128], sb2[4*128];
    __shared__ float sc[16][16], ss[16][16];
    int tid = threadIdx.x;
    int base = blockIdx.x * 16;

    for (int i = tid; i < 16*64; i += 256) sWh[i] = Wh[i];
    for (int i = tid; i < 16*128; i += 256) sWqk[i] = Wqk[i];
    if (tid < 64) sbh[tid] = bh[tid];
    if (tid < 128) sbqk[tid] = bqk[tid];
    for (int i = tid; i < 512; i += 256) { sg[i] = gamma[i]; sb2[i] = beta[i]; }
    for (int i = tid; i < 17*16; i += 256) {
        int r = i >> 4, d = i & 15;
        int f = base - 1 + r;
        xr[r][d] = (f >= 0) ? g_x[f * DIM + d] : 0.0f;
    }
    {   int i = tid >> 4, jj = tid & 15;
        int pos = (base + i) % N;
        sc[i][jj] = g_rc[pos * 16 + jj];
        ss[i][jj] = g_rs[pos * 16 + jj];
    }
    __syncthreads();
    if (tid < 17) {
        float s = 0.0f;
        #pragma unroll
        for (int d = 0; d < 16; d++) s += xr[tid][d] * xr[tid][d];
        scl[tid] = ng[0] / fmaxf(sqrtf(s) * 0.25f, 1e-5f);
    }
    __syncthreads();
    {   int i = tid >> 4, d = tid & 15;
        int flat = base + i;
        float val;
        if (d < 8) val = ((flat % N) == 0) ? 0.0f : xr[i][d] * scl[i];
        else       val = xr[i+1][d] * scl[i+1];
        nm[i][d] = val;
    }
    __syncthreads();
    for (int o = tid; o < 16 * 192; o += 256) {
        int i = o / 192, u = o % 192;
        float acc;
        if (u < 64) {
            acc = sbh[u];
            #pragma unroll
            for (int d = 0; d < 16; d++) acc += nm[i][d] * sWh[d * 64 + u];
        } else {
            int q = u - 64;
            acc = sbqk[q];
            #pragma unroll
            for (int d = 0; d < 16; d++) acc += nm[i][d] * sWqk[d * 128 + q];
        }
        float sv2 = silu_f(acc);
        int flat = base + i;
        if (u < 32)       g_v[flat * 32 + u] = sv2;
        else if (u < 64)  g_gate[flat * 32 + (u - 32)] = sv2;
        else              sqk[i][u - 64] = sv2;
    }
    __syncthreads();
    {   int i = tid >> 4;
        int d0 = (tid & 15) * 8;
        int flat = base + i;
        #pragma unroll
        for (int r = 0; r < 4; r++) {
            float* dst = (r == 0) ? g_qq : (r == 1) ? g_lq : (r == 2) ? g_kk : g_lk;
            #pragma unroll
            for (int dd = 0; dd < 8; dd += 2) {
                int d = d0 + dd;
                float v0 = sqk[i][d]   * sg[r*128 + d]   + sb2[r*128 + d];
                float v1 = sqk[i][d+1] * sg[r*128 + d+1] + sb2[r*128 + d+1];
                if (d0 < ROTD) {
                    float c = sc[i][d >> 1], s = ss[i][d >> 1];
                    float t0 = v0 * c - v1 * s;
                    v1 = v1 * c + v0 * s;
                    v0 = t0;
                }
                *(float2*)&dst[flat * 128 + d] = make_float2(v0, v1);
            }
        }
    }
}

// ---------------- K2: quadratic attention, f32x2, 512 threads ----------------
// smem floats: Qs[128][132] + Kt[128][132] + As[128][130] + Vs[128][32]
#define QS2 132
#define KT2 132
#define AS2 130
#define ATTN_SMEM ((128*QS2 + 128*KT2 + 128*AS2 + 128*32) * 4)   // 218112 B

__global__ void __launch_bounds__(512, 1) k_attn() {
    extern __shared__ float sm[];
    float* Qs = sm;                  // [row][kdim]
    float* Kt = Qs + 128 * QS2;      // [kdim][key]
    float* As = Kt + 128 * KT2;      // [row][key]
    float* Vs = As + 128 * AS2;      // [key][32]
    int tid = threadIdx.x;
    int b = blockIdx.z, g = blockIdx.y, qh = blockIdx.x;
    const int bN = b * N;

    {   // Q tile 128x128 row-major
        int row = tid >> 2;
        int d0 = (tid & 3) * 32;
        int pos = g * GSZ + qh * 128 + row;
        const float4* src = (const float4*)&g_qq[(long)(bN + pos) * 128 + d0];
        #pragma unroll
        for (int d = 0; d < 32; d += 4) {
            float4 v = (pos < N) ? src[d >> 2] : make_float4(0,0,0,0);
            *(float4*)&Qs[row * QS2 + d0 + d] = v;
        }
    }

    int tx = tid & 15;          // col group: cols 2tx+32c (+1), c=0..3
    int tyy = tid >> 4;         // rows 4tyy .. 4tyy+3
    int oi = tid >> 2;          // stage B row
    int eg = (tid & 3) * 8;     // stage B dim-octet

    unsigned long long oacc[4];
    #pragma unroll
    for (int e = 0; e < 4; e++) oacc[e] = 0ull;

    for (int kc = 0; kc < 2; kc++) {
        __syncthreads();
        {   // K chunk 128 keys, transposed; V chunk
            int col = tid & 127;
            int dg = tid >> 7;               // 0..3 -> dims [32dg,32dg+32)
            int pos = g * GSZ + kc * 128 + col;
            const float4* src = (const float4*)&g_kk[(long)(bN + pos) * 128 + dg * 32];
            #pragma unroll
            for (int d = 0; d < 32; d += 4) {
                float4 v = (pos < N) ? src[d >> 2] : make_float4(0,0,0,0);
                Kt[(dg * 32 + d + 0) * KT2 + col] = v.x;
                Kt[(dg * 32 + d + 1) * KT2 + col] = v.y;
                Kt[(dg * 32 + d + 2) * KT2 + col] = v.z;
                Kt[(dg * 32 + d + 3) * KT2 + col] = v.w;
            }
            int rr = tid >> 2;
            int e0 = (tid & 3) * 8;
            int pv = g * GSZ + kc * 128 + rr;
            const float4* vsrc = (const float4*)&g_v[(long)(bN + pv) * 32 + e0];
            float4 v0 = (pv < N) ? vsrc[0] : make_float4(0,0,0,0);
            float4 v1 = (pv < N) ? vsrc[1] : make_float4(0,0,0,0);
            *(float4*)&Vs[rr * 32 + e0]     = v0;
            *(float4*)&Vs[rr * 32 + e0 + 4] = v1;
        }
        __syncthreads();
        {   // stage A: sim rows {4tyy..+3} x cols {2tx+32c,+1}
            unsigned long long acc[4][4];
            #pragma unroll
            for (int r = 0; r < 4; r++)
                #pragma unroll
                for (int c = 0; c < 4; c++) acc[r][c] = 0ull;
            #pragma unroll 4
            for (int kk = 0; kk < 128; kk++) {
                unsigned long long kp[4];
                #pragma unroll
                for (int c = 0; c < 4; c++)
                    kp[c] = *(const unsigned long long*)&Kt[kk * KT2 + 2 * tx + 32 * c];
                #pragma unroll
                for (int r = 0; r < 4; r++) {
                    float qv = Qs[(4 * tyy + r) * QS2 + kk];
                    unsigned long long qd = pk2(qv, qv);
                    #pragma unroll
                    for (int c = 0; c < 4; c++) fma2(acc[r][c], qd, kp[c]);
                }
            }
            int kbase = g * GSZ + kc * 128;
            #pragma unroll
            for (int r = 0; r < 4; r++) {
                int row = 4 * tyy + r;
                #pragma unroll
                for (int c = 0; c < 4; c++) {
                    float2 f = up2(acc[r][c]);
                    int c0 = 2 * tx + 32 * c;
                    float s0 = fmaxf(f.x * (1.0f/256.0f), 0.0f); s0 *= s0;
                    float s1 = fmaxf(f.y * (1.0f/256.0f), 0.0f); s1 *= s1;
                    if (kbase + c0     >= N) s0 = 0.0f;
                    if (kbase + c0 + 1 >= N) s1 = 0.0f;
                    *(unsigned long long*)&As[row * AS2 + c0] = pk2(s0, s1);
                }
            }
        }
        __syncthreads();
        {   // stage B: O[oi][eg..eg+7] += A * V
            #pragma unroll 4
            for (int j = 0; j < 128; j++) {
                float aij = As[oi * AS2 + j];
                unsigned long long ad = pk2(aij, aij);
                const unsigned long long* vp = (const unsigned long long*)&Vs[j * 32 + eg];
                fma2(oacc[0], ad, vp[0]);
                fma2(oacc[1], ad, vp[1]);
                fma2(oacc[2], ad, vp[2]);
                fma2(oacc[3], ad, vp[3]);
            }
        }
    }
    int qpos = g * GSZ + qh * 128 + oi;
    if (qpos < N) {
        float* dst = &g_qo[(long)(bN + qpos) * 32 + eg];
        #pragma unroll
        for (int e = 0; e < 4; e++) {
            float2 f = up2(oacc[e]);
            *(float2*)&dst[e * 2] = f;
        }
    }
}

// ---------------- K3: linear attention KV partials (grid: 8 x B) ----------------
__global__ void k_linkvp() {
    __shared__ float slk[8][128];
    __shared__ float sv[8][32];
    int tid = threadIdx.x;
    int s = blockIdx.x, b = blockIdx.y;
    int bN = b * N;
    int p0 = s * 125, p1 = min(p0 + 125, N);
    unsigned long long acc[8];
    #pragma unroll
    for (int e = 0; e < 8; e++) acc[e] = 0ull;
    int dd = tid & 127, e0 = (tid >> 7) * 16;

    for (int pp = p0; pp < p1; pp += 8) {
        __syncthreads();
        {   int r = tid >> 5;
            int d4 = (tid & 31) * 4;
            int pos = pp + r;
            float4 v = (pos < p1) ? *(const float4*)&g_lk[(long)(bN + pos) * 128 + d4]
                                  : make_float4(0,0,0,0);
            *(float4*)&slk[r][d4] = v;
            int e = tid & 31;
            sv[r][e] = (pos < p1) ? g_v[(long)(bN + pos) * 32 + e] : 0.0f;
        }
        __syncthreads();
        #pragma unroll
        for (int r = 0; r < 8; r++) {
            float lv = slk[r][dd];
            unsigned long long ld = pk2(lv, lv);
            const ulonglong2* vp = (const ulonglong2*)&sv[r][e0];
            ulonglong2 va = vp[0], vb = vp[1], vc = vp[2], vd = vp[3];
            fma2(acc[0], ld, va.x); fma2(acc[1], ld, va.y);
            fma2(acc[2], ld, vb.x); fma2(acc[3], ld, vb.y);
            fma2(acc[4], ld, vc.x); fma2(acc[5], ld, vc.y);
            fma2(acc[6], ld, vd.x); fma2(acc[7], ld, vd.y);
        }
    }
    float* dst = &g_linkvp[((long)(b * 8 + s) * 128 + dd) * 32 + e0];
    #pragma unroll
    for (int e = 0; e < 8; e++) {
        float2 f = up2(acc[e]);
        *(float2*)&dst[e * 2] = f;
    }
}

// ---------------- K4: KV reduce + lin_out + gate + Wo + residual ----------------
__global__ void k_out(const float* __restrict__ Wo, const float* __restrict__ bo) {
    __shared__ float skv[4096];
    __shared__ float sWo[32*16];
    __shared__ float sbo[16];
    __shared__ float ovs[8][32];
    int tid = threadIdx.x;
    int b = blockIdx.y, ch = blockIdx.x;
    int bN = b * N;
    const float inv_n = 1.0f / (float)N;
    for (int i = tid; i < 1024; i += 256) {
        float4 s = make_float4(0,0,0,0);
        #pragma unroll
        for (int k2 = 0; k2 < 8; k2++) {
            float4 p = ((const float4*)&g_linkvp[(long)(b * 8 + k2) * 4096])[i];
            s.x += p.x; s.y += p.y; s.z += p.z; s.w += p.w;
        }
        ((float4*)skv)[i] = make_float4(s.x * inv_n, s.y * inv_n, s.z * inv_n, s.w * inv_n);
    }
    for (int i = tid; i < 512; i += 256) sWo[i] = Wo[i];
    if (tid < 16) sbo[tid] = bo[tid];
    __syncthreads();

    int w = tid >> 5, lane = tid & 31;
    int t0 = ch * 83, t1 = t0 + 83;   // 12*83 = 996
    for (int tok = t0 + w; tok < t1; tok += 8) {
        int tf = bN + tok;
        float4 lq4 = *(const float4*)&g_lq[(long)tf * 128 + lane * 4];
        float lqa[4] = {lq4.x, lq4.y, lq4.z, lq4.w};
        float acc = g_qo[(long)tf * 32 + lane];
        #pragma unroll
        for (int comp = 0; comp < 4; comp++) {
            #pragma unroll
            for (int src = 0; src < 32; src++) {
                float lv = __shfl_sync(0xffffffffu, lqa[comp], src);
                acc += lv * skv[(src * 4 + comp) * 32 + lane];
            }
        }
        acc *= g_gate[(long)tf * 32 + lane];
        ovs[w][lane] = acc;
        __syncwarp();
        if (lane < 16) {
            float y = sbo[lane];
            #pragma unroll
            for (int e = 0; e < 32; e++) y += ovs[w][e] * sWo[e * DIM + lane];
            g_x[(long)tf * DIM + lane] += y;
        }
        __syncwarp();
    }
}

// ---------------- K5: final norm + logits + vocab max ----------------
#define LOGITS_SMEM ((16*1024 + 1024 + 16*16) * 4)
__global__ void k_logits(const float* __restrict__ fg, const float* __restrict__ Wl,
                         const float* __restrict__ blv) {
    extern __shared__ float sm[];
    float* sW = sm;
    float* sb = sW + 16 * 1024;
    float* xn = sb + 1024;
    __shared__ float wred[8];
    __shared__ float xs[16];
    int tid = threadIdx.x;
    int base = blockIdx.x * 16;

    for (int i = tid; i < (16 * 1024) / 4; i += 256)
        ((float4*)sW)[i] = ((const float4*)Wl)[i];
    for (int i = tid; i < 1024; i += 256) sb[i] = blv[i];
    {   int tt = tid >> 4, d = tid & 15;
        xn[tt * 16 + d] = g_x[(long)(base + tt) * DIM + d];
    }
    __syncthreads();
    if (tid < 16) {
        float s = 0.0f;
        #pragma unroll
        for (int d = 0; d < 16; d++) { float v = xn[tid * 16 + d]; s += v * v; }
        xs[tid] = fg[0] / fmaxf(sqrtf(s) * 0.25f, 1e-5f);
    }
    __syncthreads();
    {   int tt = tid >> 4, d = tid & 15;
        xn[tt * 16 + d] *= xs[tt];
    }
    __syncthreads();
    int warp = tid >> 5, lane = tid & 31;
    int v0 = tid * 4;
    for (int tt = 0; tt < 16; tt++) {
        float s0 = sb[v0], s1 = sb[v0 + 1], s2 = sb[v0 + 2], s3 = sb[v0 + 3];
        #pragma unroll
        for (int d = 0; d < 16; d++) {
            float xv = xn[tt * 16 + d];
            float4 wv = *(const float4*)&sW[d * 1024 + v0];
            s0 += xv * wv.x; s1 += xv * wv.y; s2 += xv * wv.z; s3 += xv * wv.w;
        }
        float m = fmaxf(fmaxf(s0, s1), fmaxf(s2, s3));
        #pragma unroll
        for (int off = 16; off > 0; off >>= 1)
            m = fmaxf(m, __shfl_xor_sync(0xffffffff, m, off));
        if (lane == 0) wred[warp] = m;
        __syncthreads();
        if (tid == 0) {
            float mm = wred[0];
            #pragma unroll
            for (int j = 1; j < 8; j++) mm = fmaxf(mm, wred[j]);
            g_hmax[base + tt] = mm;
        }
        __syncthreads();
    }
}

// ---------------- K6: head MLP ----------------
__global__ void k_head(const float* __restrict__ W1, const float* __restrict__ b1,
                       const float* __restrict__ W2, const float* __restrict__ b2,
                       float* __restrict__ out) {
    __shared__ float red[8][32];
    __shared__ float rr[32];
    int tid = threadIdx.x;
    int b = blockIdx.x;
    int col = tid & 31, seg = tid >> 5;
    float acc = 0.0f;
    int t0 = seg * 125;
    int t1 = min(t0 + 125, N);
    for (int t = t0; t < t1; t++)
        acc += g_hmax[(long)b * N + t] * W1[t * 32 + col];
    red[seg][col] = acc;
    __syncthreads();
    if (tid < 32) {
        float s = b1[tid];
        #pragma unroll
        for (int k = 0; k < 8; k++) s += red[k][tid];
        rr[tid] = fmaxf(s, 0.0f);
    }
    __syncthreads();
    if (tid == 0) {
        float o = b2[0];
        #pragma unroll
        for (int j = 0; j < 32; j++) o += rr[j] * W2[j];
        out[b] = o;
    }
}

// ---------------- launch ----------------
extern "C" void kernel_launch(void* const* d_in, const int* in_sizes, int n_in,
                              void* d_out, int out_size) {
    const int*   kmer    = (const int*)  d_in[0];
    const float* emb     = (const float*)d_in[1];
    const float* psc     = (const float*)d_in[2];
    const float* norm_g  = (const float*)d_in[3];
    const float* Wh      = (const float*)d_in[4];
    const float* bh      = (const float*)d_in[5];
    const float* Wqk     = (const float*)d_in[6];
    const float* bqk     = (const float*)d_in[7];
    const float* gamma   = (const float*)d_in[8];
    const float* beta    = (const float*)d_in[9];
    const float* Wo      = (const float*)d_in[10];
    const float* bo      = (const float*)d_in[11];
    const float* fg      = (const float*)d_in[12];
    const float* Wl      = (const float*)d_in[13];
    const float* bl      = (const float*)d_in[14];
    const float* W1      = (const float*)d_in[15];
    const float* b1      = (const float*)d_in[16];
    const float* W2      = (const float*)d_in[17];
    const float* b2      = (const float*)d_in[18];
    float* out = (float*)d_out;

    cudaFuncSetAttribute(k_attn,   cudaFuncAttributeMaxDynamicSharedMemorySize, ATTN_SMEM);
    cudaFuncSetAttribute(k_logits, cudaFuncAttributeMaxDynamicSharedMemorySize, LOGITS_SMEM);

    k_embed<<<(BN * DIM + 255) / 256, 256>>>(kmer, emb, psc);
    k_rot<<<(N * 16 + 255) / 256, 256>>>();

    for (int l = 0; l < DEPTH; l++) {
        k_proj<<<BN / 16, 256>>>(norm_g + l,
                                 Wh + (long)l * 16 * 64, bh + (long)l * 64,
                                 Wqk + (long)l * 16 * 128, bqk + (long)l * 128,
                                 gamma + (long)l * 4 * 128, beta + (long)l * 4 * 128);
        k_attn<<<dim3(2, NG, B), 512, ATTN_SMEM>>>();
        k_linkvp<<<dim3(8, B), 256>>>();
        k_out<<<dim3(12, B), 256>>>(Wo + (long)l * 32 * DIM, bo + (long)l * DIM);
    }

    k_logits<<<BN / 16, 256, LOGITS_SMEM>>>(fg, Wl, bl);
    k_head<<<B, 256>>>(W1, b1, W2, b2, out);
    (void)in_sizes; (void)n_in; (void)out_size;
}

// round 8
// speedup vs baseline: 1.5496x; 1.1323x over previous
#include <cuda_runtime.h>
#include <math.h>

#define B 128
#define N 996
#define BN (B*N)
#define DIM 16
#define QKD 128
#define GSZ 256
#define NG 4
#define DEPTH 8
#define VOC 1024
#define ROTD 32

// ---------------- scratch ----------------
__device__ __align__(16) float g_x[BN*DIM];
__device__ __align__(16) float g_qo[BN*32];          // ungated quad attention out
__device__ __align__(16) float g_linkvp[B*8*128*32];
__device__ float g_rc[N*16];
__device__ float g_rs[N*16];
__device__ float g_hmax[BN];

#define ROT_LC 0.57564627324851142
#define POS_LC 1.1512925464970228

typedef unsigned long long ull;

__device__ __forceinline__ ull pk2(float a, float b) {
    ull r; asm("mov.b64 %0,{%1,%2};" : "=l"(r) : "f"(a), "f"(b)); return r;
}
__device__ __forceinline__ void fma2(ull& d, ull a, ull b) {
    asm("fma.rn.f32x2 %0,%1,%2,%0;" : "+l"(d) : "l"(a), "l"(b));
}
__device__ __forceinline__ float2 up2(ull v) {
    float2 f; asm("mov.b64 {%0,%1},%2;" : "=f"(f.x), "=f"(f.y) : "l"(v)); return f;
}
__device__ __forceinline__ float silu_f(float a) {
    return __fdividef(a, 1.0f + __expf(-a));
}

// proj 8 outputs [u0,u0+8) ; nmA = prev-token normed d0..7, nmB = cur normed d8..15
__device__ __forceinline__ void proj8(const float* nmA, const float* nmB,
                                      const float* __restrict__ W, int ws,
                                      const float* __restrict__ bias, int u0, float* o) {
    #pragma unroll
    for (int j = 0; j < 8; j++) o[j] = bias[u0 + j];
    #pragma unroll
    for (int d = 0; d < 8; d++) { float a = nmA[d];
        #pragma unroll
        for (int j = 0; j < 8; j++) o[j] += a * W[d * ws + u0 + j]; }
    #pragma unroll
    for (int d = 0; d < 8; d++) { float a = nmB[d];
        #pragma unroll
        for (int j = 0; j < 8; j++) o[j] += a * W[(d + 8) * ws + u0 + j]; }
}
// silu + gamma/beta + rotary (chunk-aligned); gb: [0..127]=gamma, [128..255]=beta
__device__ __forceinline__ void gbrot8(float* o, int u0, const float* __restrict__ gb, int pos) {
    #pragma unroll
    for (int jj = 0; jj < 8; jj++) o[jj] = silu_f(o[jj]);
    if (u0 < ROTD) {
        #pragma unroll
        for (int jj = 0; jj < 8; jj += 2) {
            int u = u0 + jj;
            float a = o[jj] * gb[u] + gb[128 + u];
            float b = o[jj+1] * gb[u+1] + gb[128 + u + 1];
            float c = g_rc[pos * 16 + (u >> 1)], s = g_rs[pos * 16 + (u >> 1)];
            o[jj] = a * c - b * s;
            o[jj+1] = b * c + a * s;
        }
    } else {
        #pragma unroll
        for (int jj = 0; jj < 8; jj++) { int u = u0 + jj; o[jj] = o[jj] * gb[u] + gb[128 + u]; }
    }
}

// ---------------- K0 / K0b ----------------
__global__ void k_embed(const int* __restrict__ kmer, const float* __restrict__ emb,
                        const float* __restrict__ ps) {
    int idx = blockIdx.x * blockDim.x + threadIdx.x;
    if (idx >= BN * DIM) return;
    int d = idx & 15;
    int tok = idx >> 4;
    int t = tok % N;
    int j = (d < 8) ? d : d - 8;
    float inv = (float)exp(-(double)j * POS_LC);
    float ang = (float)t * inv;
    float p = (d < 8) ? sinf(ang) : cosf(ang);
    g_x[idx] = emb[kmer[tok] * DIM + d] + p * ps[0];
}
__global__ void k_rot() {
    int idx = blockIdx.x * blockDim.x + threadIdx.x;
    if (idx >= N * 16) return;
    int t = idx >> 4, j = idx & 15;
    float inv = (float)exp(-(double)j * ROT_LC);
    float ang = (float)t * inv;
    g_rc[idx] = cosf(ang);
    g_rs[idx] = sinf(ang);
}

// ---------------- kA: fused norm+proj+quad attention ----------------
// dyn smem (floats):
#define OF_SN  0          // [257][17]
#define OF_QS  4372       // [128][132]
#define OF_KT  21268      // [128][66]  transposed K chunk
#define OF_AS  29716      // [128][66]
#define OF_VS  38164      // [64][34]
#define OF_WQK 40340      // [16][128]
#define OF_WV  42388      // [16][32]
#define OF_GBQ 42900      // gamma|beta quad_q
#define OF_GBK 43156      // gamma|beta quad_k
#define OF_BQK 43412
#define OF_BV  43540
#define KA_SMEM ((43540 + 32) * 4)   // 174288 B

__global__ void __launch_bounds__(256, 1) kA(const float* __restrict__ ng,
        const float* __restrict__ Wh, const float* __restrict__ bh,
        const float* __restrict__ Wqk, const float* __restrict__ bqk,
        const float* __restrict__ gamma, const float* __restrict__ beta) {
    extern __shared__ float s[];
    float* SN = s + OF_SN;  float* QS = s + OF_QS;  float* KT = s + OF_KT;
    float* AS = s + OF_AS;  float* VS = s + OF_VS;  float* WQ = s + OF_WQK;
    float* WV = s + OF_WV;  float* GQ = s + OF_GBQ; float* GK = s + OF_GBK;
    float* BQ = s + OF_BQK; float* BV = s + OF_BV;
    int tid = threadIdx.x;
    int qh = blockIdx.x, g = blockIdx.y, b = blockIdx.z;
    int gstart = g * GSZ;
    const int bN = b * N;

    for (int i = tid; i < 2048; i += 256) WQ[i] = Wqk[i];
    for (int i = tid; i < 512; i += 256) WV[i] = Wh[(i >> 5) * 64 + (i & 31)];
    if (tid < 128) {
        GQ[tid] = gamma[tid];       GQ[128 + tid] = beta[tid];
        GK[tid] = gamma[256 + tid]; GK[128 + tid] = beta[256 + tid];
        BQ[tid] = bqk[tid];
    }
    if (tid < 32) BV[tid] = bh[tid];
    for (int i = tid; i < 257 * 4; i += 256) {
        int r = i >> 2, d4 = (i & 3) * 4;
        int p = gstart - 1 + r;
        float4 v = make_float4(0, 0, 0, 0);
        if (p >= 0 && p < N) v = *(const float4*)&g_x[(long)(bN + p) * 16 + d4];
        SN[r*17 + d4] = v.x; SN[r*17 + d4+1] = v.y; SN[r*17 + d4+2] = v.z; SN[r*17 + d4+3] = v.w;
    }
    __syncthreads();
    float gng = ng[0];
    for (int i = tid; i < 257; i += 256) {
        float ss = 0;
        #pragma unroll
        for (int d = 0; d < 16; d++) { float v = SN[i*17 + d]; ss += v * v; }
        float scl = gng / fmaxf(sqrtf(ss) * 0.25f, 1e-5f);
        #pragma unroll
        for (int d = 0; d < 16; d++) SN[i*17 + d] *= scl;
    }
    __syncthreads();

    {   // phase1: Q tile (128 q tokens x 128 dims)
        int j = tid >> 1, h = tid & 1;
        int p = gstart + qh * 128 + j;
        int si = qh * 128 + j + 1;
        float nmA[8], nmB[8];
        bool first = (p == 0);
        #pragma unroll
        for (int d = 0; d < 8; d++) {
            nmA[d] = first ? 0.0f : SN[(si - 1) * 17 + d];
            nmB[d] = SN[si * 17 + 8 + d];
        }
        int rp = (p < N) ? p : 0;
        #pragma unroll
        for (int c = 0; c < 8; c++) {
            int u0 = h * 64 + c * 8;
            float o[8];
            proj8(nmA, nmB, WQ, 128, BQ, u0, o);
            gbrot8(o, u0, GQ, rp);
            #pragma unroll
            for (int jj = 0; jj < 8; jj += 2)
                *(float2*)&QS[j * 132 + u0 + jj] = make_float2(o[jj], o[jj+1]);
        }
    }

    ull oacc[8];
    #pragma unroll
    for (int e = 0; e < 8; e++) oacc[e] = 0ull;
    int oi = tid >> 1, eg = (tid & 1) * 16;
    int tx = tid & 7, ty = tid >> 3;

    for (int ck = 0; ck < 4; ck++) {
        __syncthreads();
        {   // build K chunk (transposed) + V chunk, 64 keys, with proj recompute
            int t = tid & 63, q4 = tid >> 6;
            int kloc = ck * 64 + t;
            int p = gstart + kloc;
            int si = kloc + 1;
            float nmA[8], nmB[8];
            bool first = (p == 0);
            #pragma unroll
            for (int d = 0; d < 8; d++) {
                nmA[d] = first ? 0.0f : SN[(si - 1) * 17 + d];
                nmB[d] = SN[si * 17 + 8 + d];
            }
            int rp = (p < N) ? p : 0;
            #pragma unroll
            for (int cc = 0; cc < 4; cc++) {
                int u0 = q4 * 32 + cc * 8;
                float o[8];
                proj8(nmA, nmB, WQ, 128, BQ, u0, o);
                gbrot8(o, u0, GK, rp);
                #pragma unroll
                for (int jj = 0; jj < 8; jj++) KT[(u0 + jj) * 66 + t] = o[jj];
            }
            {   int e0 = q4 * 8;
                float o[8];
                proj8(nmA, nmB, WV, 32, BV, e0, o);
                #pragma unroll
                for (int jj = 0; jj < 8; jj++) VS[t * 34 + e0 + jj] = silu_f(o[jj]);
            }
        }
        __syncthreads();
        {   // stage A: sim rows (4ty+r) x cols (2tx+16c)
            ull acc[4][4];
            #pragma unroll
            for (int r = 0; r < 4; r++)
                #pragma unroll
                for (int c = 0; c < 4; c++) acc[r][c] = 0ull;
            #pragma unroll 4
            for (int kk = 0; kk < 128; kk++) {
                ull kp[4];
                #pragma unroll
                for (int c = 0; c < 4; c++)
                    kp[c] = *(const ull*)&KT[kk * 66 + 2 * tx + 16 * c];
                #pragma unroll
                for (int r = 0; r < 4; r++) {
                    float qv = QS[(4 * ty + r) * 132 + kk];
                    ull qd = pk2(qv, qv);
                    #pragma unroll
                    for (int c = 0; c < 4; c++) fma2(acc[r][c], qd, kp[c]);
                }
            }
            int kb = gstart + ck * 64;
            #pragma unroll
            for (int r = 0; r < 4; r++) {
                int row = 4 * ty + r;
                #pragma unroll
                for (int c = 0; c < 4; c++) {
                    float2 f = up2(acc[r][c]);
                    int c0 = 2 * tx + 16 * c;
                    float s0 = fmaxf(f.x * (1.0f/256.0f), 0.0f); s0 *= s0;
                    float s1 = fmaxf(f.y * (1.0f/256.0f), 0.0f); s1 *= s1;
                    if (kb + c0     >= N) s0 = 0.0f;
                    if (kb + c0 + 1 >= N) s1 = 0.0f;
                    *(ull*)&AS[row * 66 + c0] = pk2(s0, s1);
                }
            }
        }
        __syncthreads();
        {   // stage B: O[oi][eg..eg+15] += A * V
            #pragma unroll 4
            for (int j = 0; j < 64; j++) {
                float a = AS[oi * 66 + j];
                ull ad = pk2(a, a);
                const ull* vp = (const ull*)&VS[j * 34 + eg];
                #pragma unroll
                for (int e = 0; e < 8; e++) fma2(oacc[e], ad, vp[e]);
            }
        }
    }
    int qp = gstart + qh * 128 + oi;
    if (qp < N) {
        float* dst = &g_qo[(long)(bN + qp) * 32 + eg];
        #pragma unroll
        for (int e = 0; e < 8; e++) { float2 f = up2(oacc[e]); *(float2*)&dst[e * 2] = f; }
    }
}

// ---------------- kB: fused lin-KV partials (grid: 8 x B) ----------------
__global__ void __launch_bounds__(256, 1) kB(const float* __restrict__ ng,
        const float* __restrict__ Wh, const float* __restrict__ bh,
        const float* __restrict__ Wqk, const float* __restrict__ bqk,
        const float* __restrict__ gamma, const float* __restrict__ beta) {
    __shared__ __align__(16) float SN[126 * 17];
    __shared__ __align__(16) float SLK[8][128];
    __shared__ __align__(16) float SV[8][32];
    __shared__ __align__(16) float WQ[2048];
    __shared__ __align__(16) float WV2[512];
    __shared__ __align__(16) float GB[256];
    __shared__ __align__(16) float BQ2[128];
    __shared__ __align__(16) float BV2[32];
    int tid = threadIdx.x;
    int sblk = blockIdx.x, b = blockIdx.y;
    const int bN = b * N;
    int p0 = sblk * 125;
    int cnt = min(125, N - p0);

    for (int i = tid; i < 2048; i += 256) WQ[i] = Wqk[i];
    for (int i = tid; i < 512; i += 256) WV2[i] = Wh[(i >> 5) * 64 + (i & 31)];
    if (tid < 128) {
        GB[tid] = gamma[3 * 128 + tid]; GB[128 + tid] = beta[3 * 128 + tid];
        BQ2[tid] = bqk[tid];
    }
    if (tid < 32) BV2[tid] = bh[tid];
    for (int i = tid; i < (cnt + 1) * 4; i += 256) {
        int r = i >> 2, d4 = (i & 3) * 4;
        int p = p0 - 1 + r;
        float4 v = make_float4(0, 0, 0, 0);
        if (p >= 0) v = *(const float4*)&g_x[(long)(bN + p) * 16 + d4];
        SN[r*17 + d4] = v.x; SN[r*17 + d4+1] = v.y; SN[r*17 + d4+2] = v.z; SN[r*17 + d4+3] = v.w;
    }
    __syncthreads();
    float gng = ng[0];
    for (int i = tid; i <= cnt; i += 256) {
        float ss = 0;
        #pragma unroll
        for (int d = 0; d < 16; d++) { float v = SN[i*17 + d]; ss += v * v; }
        float scl = gng / fmaxf(sqrtf(ss) * 0.25f, 1e-5f);
        #pragma unroll
        for (int d = 0; d < 16; d++) SN[i*17 + d] *= scl;
    }
    __syncthreads();

    ull acc[8];
    #pragma unroll
    for (int e = 0; e < 8; e++) acc[e] = 0ull;
    int dd = tid & 127, e0 = (tid >> 7) * 16;
    int r = tid >> 5, lane = tid & 31;

    for (int pp = 0; pp < cnt; pp += 8) {
        __syncthreads();
        {   int p = p0 + pp + r;
            bool valid = (pp + r) < cnt;
            int sic = valid ? (pp + r + 1) : 1;
            bool first = (p == 0);
            float nmA[8], nmB[8];
            #pragma unroll
            for (int d = 0; d < 8; d++) {
                nmA[d] = (first || !valid) ? 0.0f : SN[(sic - 1) * 17 + d];
                nmB[d] = valid ? SN[sic * 17 + 8 + d] : 0.0f;
            }
            int rp = valid ? p : 0;
            #pragma unroll
            for (int j = 0; j < 4; j++) {
                int u = lane + 32 * j;
                float o = BQ2[u];
                #pragma unroll
                for (int d = 0; d < 8; d++) o += nmA[d] * WQ[d * 128 + u];
                #pragma unroll
                for (int d = 0; d < 8; d++) o += nmB[d] * WQ[(d + 8) * 128 + u];
                o = silu_f(o);
                o = o * GB[u] + GB[128 + u];
                if (j == 0) {
                    float c = g_rc[rp * 16 + (lane >> 1)], sn2 = g_rs[rp * 16 + (lane >> 1)];
                    float part = __shfl_xor_sync(0xffffffffu, o, 1);
                    o = (lane & 1) ? (o * c + part * sn2) : (o * c - part * sn2);
                }
                SLK[r][u] = valid ? o : 0.0f;
            }
            {   float o = BV2[lane];
                #pragma unroll
                for (int d = 0; d < 8; d++) o += nmA[d] * WV2[d * 32 + lane];
                #pragma unroll
                for (int d = 0; d < 8; d++) o += nmB[d] * WV2[(d + 8) * 32 + lane];
                SV[r][lane] = valid ? silu_f(o) : 0.0f;
            }
        }
        __syncthreads();
        #pragma unroll
        for (int rr = 0; rr < 8; rr++) {
            float lv = SLK[rr][dd];
            ull ld = pk2(lv, lv);
            const ulonglong2* vp = (const ulonglong2*)&SV[rr][e0];
            ulonglong2 va = vp[0], vb = vp[1], vc = vp[2], vd = vp[3];
            fma2(acc[0], ld, va.x); fma2(acc[1], ld, va.y);
            fma2(acc[2], ld, vb.x); fma2(acc[3], ld, vb.y);
            fma2(acc[4], ld, vc.x); fma2(acc[5], ld, vc.y);
            fma2(acc[6], ld, vd.x); fma2(acc[7], ld, vd.y);
        }
    }
    float* dst = &g_linkvp[((long)(b * 8 + sblk) * 128 + dd) * 32 + e0];
    #pragma unroll
    for (int e = 0; e < 8; e++) { float2 f = up2(acc[e]); *(float2*)&dst[e * 2] = f; }
}

// ---------------- kC: fused KV-reduce + lin_out + gate + Wo + residual ----------------
__global__ void __launch_bounds__(256, 1) kC(const float* __restrict__ ng,
        const float* __restrict__ Wh, const float* __restrict__ bh,
        const float* __restrict__ Wqk, const float* __restrict__ bqk,
        const float* __restrict__ gamma, const float* __restrict__ beta,
        const float* __restrict__ Wo, const float* __restrict__ bo) {
    __shared__ __align__(16) float SN[84 * 17];
    __shared__ __align__(16) float SKV[4096];
    __shared__ __align__(16) float WQ[2048];
    __shared__ __align__(16) float WG[512];
    __shared__ __align__(16) float GB[256];
    __shared__ __align__(16) float BQ2[128];
    __shared__ __align__(16) float BG[32];
    __shared__ __align__(16) float SWO[512];
    __shared__ __align__(16) float SBO[16];
    __shared__ __align__(16) float OVS[8][32];
    int tid = threadIdx.x;
    int ch = blockIdx.x, b = blockIdx.y;
    const int bN = b * N;
    int t0 = ch * 83;

    for (int i = tid; i < 2048; i += 256) WQ[i] = Wqk[i];
    for (int i = tid; i < 512; i += 256) {
        WG[i] = Wh[(i >> 5) * 64 + 32 + (i & 31)];
        SWO[i] = Wo[i];
    }
    if (tid < 128) {
        GB[tid] = gamma[128 + tid]; GB[128 + tid] = beta[128 + tid];
        BQ2[tid] = bqk[tid];
    }
    if (tid < 32) BG[tid] = bh[32 + tid];
    if (tid < 16) SBO[tid] = bo[tid];
    const float inv_n = 1.0f / (float)N;
    for (int i = tid; i < 1024; i += 256) {
        float4 ssum = make_float4(0, 0, 0, 0);
        #pragma unroll
        for (int k2 = 0; k2 < 8; k2++) {
            float4 p = ((const float4*)&g_linkvp[(long)(b * 8 + k2) * 4096])[i];
            ssum.x += p.x; ssum.y += p.y; ssum.z += p.z; ssum.w += p.w;
        }
        ((float4*)SKV)[i] = make_float4(ssum.x * inv_n, ssum.y * inv_n, ssum.z * inv_n, ssum.w * inv_n);
    }
    for (int i = tid; i < 84 * 4; i += 256) {
        int r = i >> 2, d4 = (i & 3) * 4;
        int p = t0 - 1 + r;
        float4 v = make_float4(0, 0, 0, 0);
        if (p >= 0 && p < N) v = *(const float4*)&g_x[(long)(bN + p) * 16 + d4];
        SN[r*17 + d4] = v.x; SN[r*17 + d4+1] = v.y; SN[r*17 + d4+2] = v.z; SN[r*17 + d4+3] = v.w;
    }
    __syncthreads();
    float gng = ng[0];
    for (int i = tid; i < 84; i += 256) {
        float ss = 0;
        #pragma unroll
        for (int d = 0; d < 16; d++) { float v = SN[i*17 + d]; ss += v * v; }
        float scl = gng / fmaxf(sqrtf(ss) * 0.25f, 1e-5f);
        #pragma unroll
        for (int d = 0; d < 16; d++) SN[i*17 + d] *= scl;
    }
    __syncthreads();

    int w = tid >> 5, lane = tid & 31;
    for (int tok = t0 + w; tok < t0 + 83; tok += 8) {
        int si = tok - t0 + 1;
        bool first = (tok == 0);
        float nmA[8], nmB[8];
        #pragma unroll
        for (int d = 0; d < 8; d++) {
            nmA[d] = first ? 0.0f : SN[(si - 1) * 17 + d];
            nmB[d] = SN[si * 17 + 8 + d];
        }
        float lq4[4];
        #pragma unroll
        for (int j = 0; j < 4; j++) {
            int u = lane + 32 * j;
            float o = BQ2[u];
            #pragma unroll
            for (int d = 0; d < 8; d++) o += nmA[d] * WQ[d * 128 + u];
            #pragma unroll
            for (int d = 0; d < 8; d++) o += nmB[d] * WQ[(d + 8) * 128 + u];
            o = silu_f(o);
            o = o * GB[u] + GB[128 + u];
            if (j == 0) {
                float c = g_rc[tok * 16 + (lane >> 1)], sn2 = g_rs[tok * 16 + (lane >> 1)];
                float part = __shfl_xor_sync(0xffffffffu, o, 1);
                o = (lane & 1) ? (o * c + part * sn2) : (o * c - part * sn2);
            }
            lq4[j] = o;
        }
        float gt;
        {   float o = BG[lane];
            #pragma unroll
            for (int d = 0; d < 8; d++) o += nmA[d] * WG[d * 32 + lane];
            #pragma unroll
            for (int d = 0; d < 8; d++) o += nmB[d] * WG[(d + 8) * 32 + lane];
            gt = silu_f(o);
        }
        float acc = g_qo[(long)(bN + tok) * 32 + lane];
        #pragma unroll
        for (int j = 0; j < 4; j++) {
            #pragma unroll
            for (int src = 0; src < 32; src++) {
                float lv = __shfl_sync(0xffffffffu, lq4[j], src);
                acc += lv * SKV[(src + 32 * j) * 32 + lane];
            }
        }
        acc *= gt;
        OVS[w][lane] = acc;
        __syncwarp();
        if (lane < 16) {
            float y = SBO[lane];
            #pragma unroll
            for (int e = 0; e < 32; e++) y += OVS[w][e] * SWO[e * 16 + lane];
            g_x[(long)(bN + tok) * 16 + lane] += y;
        }
        __syncwarp();
    }
}

// ---------------- k_logits / k_head ----------------
#define LOGITS_SMEM ((16*1024 + 1024 + 16*16) * 4)
__global__ void k_logits(const float* __restrict__ fg, const float* __restrict__ Wl,
                         const float* __restrict__ blv) {
    extern __shared__ float sm[];
    float* sW = sm;
    float* sb = sW + 16 * 1024;
    float* xn = sb + 1024;
    __shared__ float wred[8];
    __shared__ float xs[16];
    int tid = threadIdx.x;
    int base = blockIdx.x * 16;
    for (int i = tid; i < (16 * 1024) / 4; i += 256)
        ((float4*)sW)[i] = ((const float4*)Wl)[i];
    for (int i = tid; i < 1024; i += 256) sb[i] = blv[i];
    {   int tt = tid >> 4, d = tid & 15;
        xn[tt * 16 + d] = g_x[(long)(base + tt) * DIM + d];
    }
    __syncthreads();
    if (tid < 16) {
        float ss = 0;
        #pragma unroll
        for (int d = 0; d < 16; d++) { float v = xn[tid * 16 + d]; ss += v * v; }
        xs[tid] = fg[0] / fmaxf(sqrtf(ss) * 0.25f, 1e-5f);
    }
    __syncthreads();
    {   int tt = tid >> 4, d = tid & 15;
        xn[tt * 16 + d] *= xs[tt];
    }
    __syncthreads();
    int warp = tid >> 5, lane = tid & 31;
    int v0 = tid * 4;
    for (int tt = 0; tt < 16; tt++) {
        float s0 = sb[v0], s1 = sb[v0+1], s2 = sb[v0+2], s3 = sb[v0+3];
        #pragma unroll
        for (int d = 0; d < 16; d++) {
            float xv = xn[tt * 16 + d];
            float4 wv = *(const float4*)&sW[d * 1024 + v0];
            s0 += xv * wv.x; s1 += xv * wv.y; s2 += xv * wv.z; s3 += xv * wv.w;
        }
        float m = fmaxf(fmaxf(s0, s1), fmaxf(s2, s3));
        #pragma unroll
        for (int off = 16; off > 0; off >>= 1)
            m = fmaxf(m, __shfl_xor_sync(0xffffffff, m, off));
        if (lane == 0) wred[warp] = m;
        __syncthreads();
        if (tid == 0) {
            float mm = wred[0];
            #pragma unroll
            for (int j = 1; j < 8; j++) mm = fmaxf(mm, wred[j]);
            g_hmax[base + tt] = mm;
        }
        __syncthreads();
    }
}
__global__ void k_head(const float* __restrict__ W1, const float* __restrict__ b1,
                       const float* __restrict__ W2, const float* __restrict__ b2,
                       float* __restrict__ out) {
    __shared__ float red[8][32];
    __shared__ float rr[32];
    int tid = threadIdx.x;
    int b = blockIdx.x;
    int col = tid & 31, seg = tid >> 5;
    float acc = 0.0f;
    int t0 = seg * 125;
    int t1 = min(t0 + 125, N);
    for (int t = t0; t < t1; t++)
        acc += g_hmax[(long)b * N + t] * W1[t * 32 + col];
    red[seg][col] = acc;
    __syncthreads();
    if (tid < 32) {
        float ss = b1[tid];
        #pragma unroll
        for (int k = 0; k < 8; k++) ss += red[k][tid];
        rr[tid] = fmaxf(ss, 0.0f);
    }
    __syncthreads();
    if (tid == 0) {
        float o = b2[0];
        #pragma unroll
        for (int j = 0; j < 32; j++) o += rr[j] * W2[j];
        out[b] = o;
    }
}

// ---------------- launch ----------------
extern "C" void kernel_launch(void* const* d_in, const int* in_sizes, int n_in,
                              void* d_out, int out_size) {
    const int*   kmer    = (const int*)  d_in[0];
    const float* emb     = (const float*)d_in[1];
    const float* psc     = (const float*)d_in[2];
    const float* norm_g  = (const float*)d_in[3];
    const float* Wh      = (const float*)d_in[4];
    const float* bh      = (const float*)d_in[5];
    const float* Wqk     = (const float*)d_in[6];
    const float* bqk     = (const float*)d_in[7];
    const float* gamma   = (const float*)d_in[8];
    const float* beta    = (const float*)d_in[9];
    const float* Wo      = (const float*)d_in[10];
    const float* bo      = (const float*)d_in[11];
    const float* fg      = (const float*)d_in[12];
    const float* Wl      = (const float*)d_in[13];
    const float* bl      = (const float*)d_in[14];
    const float* W1      = (const float*)d_in[15];
    const float* b1      = (const float*)d_in[16];
    const float* W2      = (const float*)d_in[17];
    const float* b2      = (const float*)d_in[18];
    float* out = (float*)d_out;

    cudaFuncSetAttribute(kA, cudaFuncAttributeMaxDynamicSharedMemorySize, KA_SMEM);
    cudaFuncSetAttribute(k_logits, cudaFuncAttributeMaxDynamicSharedMemorySize, LOGITS_SMEM);

    k_embed<<<(BN * DIM + 255) / 256, 256>>>(kmer, emb, psc);
    k_rot<<<(N * 16 + 255) / 256, 256>>>();

    for (int l = 0; l < DEPTH; l++) {
        const float* Whl = Wh + (long)l * 16 * 64;
        const float* bhl = bh + (long)l * 64;
        const float* Wql = Wqk + (long)l * 16 * 128;
        const float* bql = bqk + (long)l * 128;
        const float* gml = gamma + (long)l * 4 * 128;
        const float* btl = beta + (long)l * 4 * 128;
        kA<<<dim3(2, NG, B), 256, KA_SMEM>>>(norm_g + l, Whl, bhl, Wql, bql, gml, btl);
        kB<<<dim3(8, B), 256>>>(norm_g + l, Whl, bhl, Wql, bql, gml, btl);
        kC<<<dim3(12, B), 256>>>(norm_g + l, Whl, bhl, Wql, bql, gml, btl,
                                 Wo + (long)l * 32 * DIM, bo + (long)l * DIM);
    }

    k_logits<<<BN / 16, 256, LOGITS_SMEM>>>(fg, Wl, bl);
    k_head<<<B, 256>>>(W1, b1, W2, b2, out);
    (void)in_sizes; (void)n_in; (void)out_size;
}